// round 10
// baseline (speedup 1.0000x reference)
#include <cuda_runtime.h>
#include <math.h>
#include <cstdint>

#define NB 16
#define NL 1024
#define NC 4
#define NE 256
#define NH 8
#define NE3 768
#define LN_EPS 1e-5f
// (1/sqrt(32)) * log2(e): exp2-domain softmax scale, folded into Q in the GEMM
#define SC2F 0.25506298365213554f

// Scratch (static device globals — no dynamic allocation allowed)
__device__ __align__(16) float    g_emb[NB * NL * NE];        // fp32 residual
__device__ __align__(16) uint32_t g_embh[NB * NL * NE / 2];   // fp16x2 LN output
__device__ __align__(16) uint32_t g_qkvh[NB * NL * NE3 / 2];  // fp16x2 qkv (q pre-scaled)
__device__ __align__(16) uint32_t g_ctxh[NB * NL * NE / 2];   // fp16x2 context
__device__ __align__(16) uint32_t g_wqkvh[NE3 * NE / 2];      // in_proj_w fp16x2
__device__ __align__(16) uint32_t g_wouth[NE * NE / 2];       // out_w fp16x2

// ---------------------------------------------------------------------------
// PTX helpers (plain ISA only — ptxas targets sm_103 without 'a' features)
// ---------------------------------------------------------------------------
#define MMA_F16(c, a, b)                                                       \
    asm volatile("mma.sync.aligned.m16n8k16.row.col.f32.f16.f16.f32 "          \
        "{%0,%1,%2,%3}, {%4,%5,%6,%7}, {%8,%9}, {%0,%1,%2,%3};"                \
        : "+f"((c)[0]), "+f"((c)[1]), "+f"((c)[2]), "+f"((c)[3])               \
        : "r"((a)[0]), "r"((a)[1]), "r"((a)[2]), "r"((a)[3]),                  \
          "r"((b)[0]), "r"((b)[1]))

#define PACKF16(r, lo, hi)                                                     \
    asm("cvt.rn.f16x2.f32 %0, %1, %2;" : "=r"(r) : "f"(hi), "f"(lo))

// two fp16 exp2 in ONE MUFU op (halves MUFU pressure vs exp2f)
#define EX2H2(r) asm("ex2.approx.f16x2 %0, %0;" : "+r"(r))

#define CP_ASYNC16(dst_u32, src_ptr)                                           \
    asm volatile("cp.async.cg.shared.global [%0], [%1], 16;"                   \
                 :: "r"(dst_u32), "l"(src_ptr))
#define CP_COMMIT() asm volatile("cp.async.commit_group;" ::: "memory")
#define CP_WAIT1()  asm volatile("cp.async.wait_group 1;" ::: "memory")
#define CP_WAIT0()  asm volatile("cp.async.wait_group 0;" ::: "memory")

#define LDSM4(r0, r1, r2, r3, addr)                                            \
    asm volatile("ldmatrix.sync.aligned.m8n8.x4.shared.b16 {%0,%1,%2,%3}, [%4];" \
        : "=r"(r0), "=r"(r1), "=r"(r2), "=r"(r3) : "r"(addr))
#define LDSM4T(r0, r1, r2, r3, addr)                                           \
    asm volatile("ldmatrix.sync.aligned.m8n8.x4.trans.shared.b16 {%0,%1,%2,%3}, [%4];" \
        : "=r"(r0), "=r"(r1), "=r"(r2), "=r"(r3) : "r"(addr))

// ---------------------------------------------------------------------------
// Kernel 0: fp32 -> packed fp16x2 conversion of BOTH weight matrices (1 launch)
// ---------------------------------------------------------------------------
#define NW1 (NE3 * NE / 2)
#define NW2 (NE * NE / 2)
__global__ void cvtw_kernel(const float* __restrict__ src1,
                            const float* __restrict__ src2,
                            uint32_t* __restrict__ dst1,
                            uint32_t* __restrict__ dst2) {
    int i = blockIdx.x * 256 + threadIdx.x;
    if (i < NW1) {
        uint32_t w;
        PACKF16(w, src1[2 * i], src1[2 * i + 1]);
        dst1[i] = w;
    } else {
        int j = i - NW1;
        if (j < NW2) {
            uint32_t w;
            PACKF16(w, src2[2 * j], src2[2 * j + 1]);
            dst2[j] = w;
        }
    }
}

// ---------------------------------------------------------------------------
// Kernel 1: embedding gather + bias + LayerNorm.  Warp per row (8 rows/block):
// warp-shuffle reduction only — no barrier, no smem.
// ---------------------------------------------------------------------------
__global__ void __launch_bounds__(256) embed_ln_kernel(
    const int* __restrict__ seq, const float* __restrict__ emb_w,
    const float* __restrict__ emb_b) {
    const int wid = threadIdx.x >> 5, lane = threadIdx.x & 31;
    const int row = blockIdx.x * 8 + wid;
    const int l = row & (NL - 1);
    const int c = seq[row];

    float v[8];
    float s = 0.f, q = 0.f;
#pragma unroll
    for (int i = 0; i < 8; i++) {
        const int e = lane + 32 * i;
        v[i] = emb_w[(l * NE + e) * NC + c] + emb_b[l * NE + e];
        s += v[i];
        q += v[i] * v[i];
    }
#pragma unroll
    for (int o = 16; o > 0; o >>= 1) {
        s += __shfl_xor_sync(0xffffffffu, s, o);
        q += __shfl_xor_sync(0xffffffffu, q, o);
    }
    const float mean = s * (1.f / NE);
    const float var = q * (1.f / NE) - mean * mean;
    const float r = rsqrtf(var + LN_EPS);
#pragma unroll
    for (int i = 0; i < 8; i++) {
        const int e = lane + 32 * i;
        const float y = (v[i] - mean) * r;
        g_emb[(size_t)row * NE + e] = y;
        const float y1 = __shfl_down_sync(0xffffffffu, y, 1);
        if ((lane & 1) == 0) {
            uint32_t w;
            PACKF16(w, y, y1);
            g_embh[(size_t)row * (NE / 2) + (e >> 1)] = w;
        }
    }
}

// ---------------------------------------------------------------------------
// Kernel 2: QKV fp16 GEMM.  Block tile 128x128, 8 warps (4m x 2n) of 32x64.
// Single barrier per K-chunk: wait -> sync -> issue(next) -> compute.
// Q columns (col<256) scaled by SC2F in epilogue (exp2-domain softmax).
// ---------------------------------------------------------------------------
#define GEMM_SMEM_WORDS (4 * 4608)     // As[2][128][36] + Bs[2][128][36]

__global__ void __launch_bounds__(256) gemm_qkv_kernel(
    const uint32_t* __restrict__ A, const uint32_t* __restrict__ W,
    const float* __restrict__ bias, uint32_t* __restrict__ C16) {
    extern __shared__ uint32_t sm[];
    const int tid = threadIdx.x, wid = tid >> 5, lane = tid & 31;
    const int g = lane >> 2, tg = lane & 3;
    const int m0 = blockIdx.y * 128, n0 = blockIdx.x * 128;
    const int wm = (wid & 3) * 32, wn = (wid >> 2) * 64;
    const uint32_t smb = (uint32_t)__cvta_generic_to_shared(sm);
    const int a_r = lane & 15, a_c = (lane >> 4) * 4;
    const int b_r = (lane & 7) + ((lane >> 4) << 3), b_c = ((lane >> 3) & 1) * 4;

    float acc[2][8][4];
#pragma unroll
    for (int mt = 0; mt < 2; mt++)
#pragma unroll
        for (int nt = 0; nt < 8; nt++)
#pragma unroll
            for (int j = 0; j < 4; j++) acc[mt][nt][j] = 0.f;

#define QKV_ISSUE(cc)                                                          \
    do {                                                                       \
        const int _s = (cc) & 1;                                               \
        _Pragma("unroll")                                                      \
        for (int it = 0; it < 4; it++) {                                       \
            int t = tid + it * 256;                                            \
            int r = t >> 3, c = (t & 7) * 4;                                   \
            CP_ASYNC16(smb + (uint32_t)(_s * 4608 + r * 36 + c) * 4,           \
                       &A[(size_t)(m0 + r) * 128 + (cc) * 32 + c]);            \
        }                                                                      \
        _Pragma("unroll")                                                      \
        for (int it = 0; it < 4; it++) {                                       \
            int t = tid + it * 256;                                            \
            int r = t >> 3, c = (t & 7) * 4;                                   \
            CP_ASYNC16(smb + (uint32_t)(9216 + _s * 4608 + r * 36 + c) * 4,    \
                       &W[(size_t)(n0 + r) * 128 + (cc) * 32 + c]);            \
        }                                                                      \
    } while (0)

    QKV_ISSUE(0);
    CP_COMMIT();

#pragma unroll
    for (int cchunk = 0; cchunk < 4; cchunk++) {
        CP_WAIT0();
        __syncthreads();            // buffer 'cchunk' visible; stale buffer free
        if (cchunk < 3) {
            QKV_ISSUE(cchunk + 1);
            CP_COMMIT();
        }
        const uint32_t abase = smb + (uint32_t)((cchunk & 1) * 4608) * 4;
        const uint32_t bbase = smb + (uint32_t)(9216 + (cchunk & 1) * 4608) * 4;
#pragma unroll
        for (int ks = 0; ks < 4; ks++) {
            const int k0 = ks * 8;
            uint32_t af[2][4];
#pragma unroll
            for (int mt = 0; mt < 2; mt++)
                LDSM4(af[mt][0], af[mt][1], af[mt][2], af[mt][3],
                      abase + (uint32_t)((wm + mt * 16 + a_r) * 36 + k0 + a_c) * 4);
            uint32_t bf[8][2];
#pragma unroll
            for (int ntp = 0; ntp < 4; ntp++)
                LDSM4(bf[2 * ntp][0], bf[2 * ntp][1], bf[2 * ntp + 1][0], bf[2 * ntp + 1][1],
                      bbase + (uint32_t)((wn + ntp * 16 + b_r) * 36 + k0 + b_c) * 4);
#pragma unroll
            for (int mt = 0; mt < 2; mt++)
#pragma unroll
                for (int nt = 0; nt < 8; nt++)
                    MMA_F16(acc[mt][nt], af[mt], bf[nt]);
        }
    }
#undef QKV_ISSUE

#pragma unroll
    for (int mt = 0; mt < 2; mt++)
#pragma unroll
        for (int nt = 0; nt < 8; nt++) {
            const int row = m0 + wm + mt * 16 + g;
            const int col = n0 + wn + nt * 8 + tg * 2;
            const float scl = (col < 256) ? SC2F : 1.0f;  // Q gets softmax scale
            const float b0 = bias[col], b1 = bias[col + 1];
            const int colw = col >> 1;
            uint32_t w0, w1;
            PACKF16(w0, (acc[mt][nt][0] + b0) * scl, (acc[mt][nt][1] + b1) * scl);
            PACKF16(w1, (acc[mt][nt][2] + b0) * scl, (acc[mt][nt][3] + b1) * scl);
            C16[(size_t)row * 384 + colw] = w0;
            C16[(size_t)(row + 8) * 384 + colw] = w1;
        }
}

// ---------------------------------------------------------------------------
// Kernel 3: fused flash attention.  fp16 MMA; no-max exp2 softmax via
// ex2.approx.f16x2; row-sum l via MMA against all-ones B.  128-key chunks,
// triple-buffered in DYNAMIC smem (2 halves per chunk -> 8 barriers total).
// Block = (b, h, 128-q tile), 256 thr = 8 warps; Q frags hoisted.
// Dyn smem layout (words): Qs[128][20] @0, Ks[3][128][20] @2560, Vs @10240.
// ---------------------------------------------------------------------------
#define ATTN_SMEM_BYTES ((2560 + 7680 + 7680) * 4)   // 71680

__global__ void __launch_bounds__(256) attn_kernel() {
    extern __shared__ uint32_t sm[];
    const int qb = blockIdx.x * 128;
    const int h  = blockIdx.y;
    const int b  = blockIdx.z;
    const int tid = threadIdx.x, wid = tid >> 5, lane = tid & 31;
    const int g = lane >> 2, tg = lane & 3;
    const int qw = wid * 16;

    const uint32_t smb = (uint32_t)__cvta_generic_to_shared(sm);
    const uint32_t smQ = smb;
    const uint32_t smK = smb + 2560 * 4;
    const uint32_t smV = smb + 10240 * 4;

#pragma unroll
    for (int it = 0; it < 2; it++) {
        int t = tid + it * 256;
        int r = t >> 2, c4 = (t & 3) * 4;
        *(uint4*)&sm[r * 20 + c4] =
            *(const uint4*)&g_qkvh[(size_t)(b * NL + qb + r) * 384 + h * 16 + c4];
    }

    const uint32_t q_ad = smQ + (uint32_t)((qw + (lane & 15)) * 20 + ((lane >> 4) << 2)) * 4;
    const uint32_t k_ad = smK + (uint32_t)(((lane & 7) + ((lane >> 4) << 3)) * 20 +
                                           (((lane >> 3) & 1) << 2)) * 4;
    const uint32_t v_ad = smV + (uint32_t)((lane & 15) * 20 + ((lane >> 4) << 2)) * 4;

    float o[4][4], lacc[4];
#pragma unroll
    for (int nt = 0; nt < 4; nt++)
#pragma unroll
        for (int j = 0; j < 4; j++) o[nt][j] = 0.f;
#pragma unroll
    for (int j = 0; j < 4; j++) lacc[j] = 0.f;
    const uint32_t ones2[2] = {0x3C003C00u, 0x3C003C00u};  // fp16 1.0 x2

    // 128-key chunk loader: 256 threads, each 2 uint4 for K + 2 for V
    const int fr = tid >> 1, fc = (tid & 1) * 8;

#define ATTN_ISSUE(kb, buf)                                                    \
    do {                                                                       \
        size_t base = (size_t)(b * NL + (kb) + fr) * 384 + h * 16 + fc;        \
        uint32_t off = (uint32_t)((buf) * 2560 + fr * 20 + fc) * 4;            \
        CP_ASYNC16(smK + off, &g_qkvh[base + 128]);                            \
        CP_ASYNC16(smK + off + 16, &g_qkvh[base + 132]);                       \
        CP_ASYNC16(smV + off, &g_qkvh[base + 256]);                            \
        CP_ASYNC16(smV + off + 16, &g_qkvh[base + 260]);                       \
    } while (0)

    ATTN_ISSUE(0, 0);
    CP_COMMIT();
    ATTN_ISSUE(128, 1);
    CP_COMMIT();
    __syncthreads();               // Qs visible -> load Q fragments once

    uint32_t qf[2][4];
#pragma unroll
    for (int ks = 0; ks < 2; ks++)
        LDSM4(qf[ks][0], qf[ks][1], qf[ks][2], qf[ks][3], q_ad + ks * 32);

    int buf = 0;
#pragma unroll 1
    for (int it = 0; it < 8; it++) {
        if (it >= 6) CP_WAIT0(); else CP_WAIT1();
        __syncthreads();           // buffer 'it' visible; buffer (it-1)%3 free
        if (it < 6) {
            ATTN_ISSUE((it + 2) * 128, (buf + 2) % 3);
            CP_COMMIT();
        }

#pragma unroll
        for (int kh = 0; kh < 2; kh++) {       // two 64-key halves
            const uint32_t boff = (uint32_t)(buf * 10240 + kh * 5120);

            // ---- S = Q K^T : 8 n-tiles of 8 keys, 2 k16 steps ----
            float s[8][4];
#pragma unroll
            for (int nt = 0; nt < 8; nt++)
#pragma unroll
                for (int j = 0; j < 4; j++) s[nt][j] = 0.f;
#pragma unroll
            for (int ks = 0; ks < 2; ks++) {
#pragma unroll
                for (int ntp = 0; ntp < 4; ntp++) {
                    uint32_t b0, b1, b2, b3;
                    LDSM4(b0, b1, b2, b3, k_ad + boff + ntp * 1280 + ks * 32);
                    uint32_t bfa[2] = {b0, b1};
                    uint32_t bfb[2] = {b2, b3};
                    MMA_F16(s[2 * ntp], qf[ks], bfa);
                    MMA_F16(s[2 * ntp + 1], qf[ks], bfb);
                }
            }

            // ---- pack to fp16 pairs, p = exp2 via f16x2 MUFU (2 per op) ----
            uint32_t p[8][2];
#pragma unroll
            for (int nt = 0; nt < 8; nt++) {
                PACKF16(p[nt][0], s[nt][0], s[nt][1]);   // row g
                PACKF16(p[nt][1], s[nt][2], s[nt][3]);   // row g+8
                EX2H2(p[nt][0]);
                EX2H2(p[nt][1]);
            }

            // ---- O += P V ; l += P @ ones (row sum via MMA, no shuffles) ----
#pragma unroll
            for (int ks = 0; ks < 4; ks++) {          // 16 keys per step
                uint32_t ap[4] = {p[2 * ks][0], p[2 * ks][1],
                                  p[2 * ks + 1][0], p[2 * ks + 1][1]};
                MMA_F16(lacc, ap, ones2);
#pragma unroll
                for (int ntp = 0; ntp < 2; ntp++) {
                    uint32_t b0, b1, b2, b3;
                    LDSM4T(b0, b1, b2, b3, v_ad + boff + ks * 1280 + ntp * 32);
                    uint32_t bfa[2] = {b0, b1};
                    uint32_t bfb[2] = {b2, b3};
                    MMA_F16(o[2 * ntp], ap, bfa);
                    MMA_F16(o[2 * ntp + 1], ap, bfb);
                }
            }
        }
        buf = (buf + 1) % 3;
    }
#undef ATTN_ISSUE

    // lacc[0] = full row-g sum, lacc[2] = full row-(g+8) sum (all lanes agree)
    const float inv0 = 1.f / lacc[0];
    const float inv1 = 1.f / lacc[2];
    const int row = b * NL + qb + qw + g;
#pragma unroll
    for (int nt = 0; nt < 4; nt++) {
        const int colw = h * 16 + nt * 4 + tg;
        uint32_t w0, w1;
        PACKF16(w0, o[nt][0] * inv0, o[nt][1] * inv0);
        PACKF16(w1, o[nt][2] * inv1, o[nt][3] * inv1);
        g_ctxh[(size_t)row * 128 + colw] = w0;
        g_ctxh[(size_t)(row + 8) * 128 + colw] = w1;
    }
}

// ---------------------------------------------------------------------------
// Kernel 4: fused out-projection + residual + LayerNorm -> d_out.
// Block tile 64x256 (full rows), 8 warps (2m x 4n) of 32x64; K = 256.
// Single barrier per K-chunk.
// ---------------------------------------------------------------------------
#define OP_SMEM_WORDS (2 * 2304 + 2 * 9216)

__global__ void __launch_bounds__(256) outproj_ln_kernel(
    const uint32_t* __restrict__ Ctx, const uint32_t* __restrict__ Wh,
    const float* __restrict__ bias, float* __restrict__ outp) {
    extern __shared__ uint32_t sm[];
    __shared__ float s_sum[64][4], s_sq[64][4];
    const int tid = threadIdx.x, wid = tid >> 5, lane = tid & 31;
    const int g = lane >> 2, tg = lane & 3;
    const int m0 = blockIdx.x * 64;
    const int wm = (wid & 1) * 32, wn = (wid >> 1) * 64, nw = wid >> 1;
    const uint32_t smb = (uint32_t)__cvta_generic_to_shared(sm);
    const int a_r = lane & 15, a_c = (lane >> 4) * 4;
    const int b_r = (lane & 7) + ((lane >> 4) << 3), b_c = ((lane >> 3) & 1) * 4;

    float acc[2][8][4];
#pragma unroll
    for (int mt = 0; mt < 2; mt++)
#pragma unroll
        for (int nt = 0; nt < 8; nt++)
#pragma unroll
            for (int j = 0; j < 4; j++) acc[mt][nt][j] = 0.f;

#define OP_ISSUE(cc)                                                           \
    do {                                                                       \
        const int _s = (cc) & 1;                                               \
        _Pragma("unroll")                                                      \
        for (int it = 0; it < 2; it++) {                                       \
            int t = tid + it * 256;                                            \
            int r = t >> 3, c = (t & 7) * 4;                                   \
            CP_ASYNC16(smb + (uint32_t)(_s * 2304 + r * 36 + c) * 4,           \
                       &Ctx[(size_t)(m0 + r) * 128 + (cc) * 32 + c]);          \
        }                                                                      \
        _Pragma("unroll")                                                      \
        for (int it = 0; it < 8; it++) {                                       \
            int t = tid + it * 256;                                            \
            int r = t >> 3, c = (t & 7) * 4;                                   \
            CP_ASYNC16(smb + (uint32_t)(4608 + _s * 9216 + r * 36 + c) * 4,    \
                       &Wh[(size_t)r * 128 + (cc) * 32 + c]);                  \
        }                                                                      \
    } while (0)

    OP_ISSUE(0);
    CP_COMMIT();

#pragma unroll
    for (int cchunk = 0; cchunk < 4; cchunk++) {
        CP_WAIT0();
        __syncthreads();
        if (cchunk < 3) {
            OP_ISSUE(cchunk + 1);
            CP_COMMIT();
        }
        const uint32_t abase = smb + (uint32_t)((cchunk & 1) * 2304) * 4;
        const uint32_t bbase = smb + (uint32_t)(4608 + (cchunk & 1) * 9216) * 4;
#pragma unroll
        for (int ks = 0; ks < 4; ks++) {
            const int k0 = ks * 8;
            uint32_t af[2][4];
#pragma unroll
            for (int mt = 0; mt < 2; mt++)
                LDSM4(af[mt][0], af[mt][1], af[mt][2], af[mt][3],
                      abase + (uint32_t)((wm + mt * 16 + a_r) * 36 + k0 + a_c) * 4);
            uint32_t bf[8][2];
#pragma unroll
            for (int ntp = 0; ntp < 4; ntp++)
                LDSM4(bf[2 * ntp][0], bf[2 * ntp][1], bf[2 * ntp + 1][0], bf[2 * ntp + 1][1],
                      bbase + (uint32_t)((wn + ntp * 16 + b_r) * 36 + k0 + b_c) * 4);
#pragma unroll
            for (int mt = 0; mt < 2; mt++)
#pragma unroll
                for (int nt = 0; nt < 8; nt++)
                    MMA_F16(acc[mt][nt], af[mt], bf[nt]);
        }
    }
#undef OP_ISSUE

#pragma unroll
    for (int mt = 0; mt < 2; mt++)
#pragma unroll
        for (int nt = 0; nt < 8; nt++) {
            const int col = wn + nt * 8 + tg * 2;
            const int rA = m0 + wm + mt * 16 + g;
            const float b0 = bias[col], b1 = bias[col + 1];
            float2 eA = *(const float2*)&g_emb[(size_t)rA * 256 + col];
            float2 eB = *(const float2*)&g_emb[(size_t)(rA + 8) * 256 + col];
            acc[mt][nt][0] += b0 + eA.x;
            acc[mt][nt][1] += b1 + eA.y;
            acc[mt][nt][2] += b0 + eB.x;
            acc[mt][nt][3] += b1 + eB.y;
        }

#pragma unroll
    for (int mt = 0; mt < 2; mt++) {
        float sA = 0.f, qA = 0.f, sB = 0.f, qB = 0.f;
#pragma unroll
        for (int nt = 0; nt < 8; nt++) {
            sA += acc[mt][nt][0] + acc[mt][nt][1];
            qA += acc[mt][nt][0] * acc[mt][nt][0] + acc[mt][nt][1] * acc[mt][nt][1];
            sB += acc[mt][nt][2] + acc[mt][nt][3];
            qB += acc[mt][nt][2] * acc[mt][nt][2] + acc[mt][nt][3] * acc[mt][nt][3];
        }
#pragma unroll
        for (int off = 1; off < 4; off <<= 1) {
            sA += __shfl_xor_sync(0xffffffffu, sA, off);
            qA += __shfl_xor_sync(0xffffffffu, qA, off);
            sB += __shfl_xor_sync(0xffffffffu, sB, off);
            qB += __shfl_xor_sync(0xffffffffu, qB, off);
        }
        if (tg == 0) {
            const int lr = wm + mt * 16 + g;
            s_sum[lr][nw] = sA; s_sq[lr][nw] = qA;
            s_sum[lr + 8][nw] = sB; s_sq[lr + 8][nw] = qB;
        }
    }
    __syncthreads();

#pragma unroll
    for (int mt = 0; mt < 2; mt++) {
        const int lrA = wm + mt * 16 + g, lrB = lrA + 8;
        float tsA = s_sum[lrA][0] + s_sum[lrA][1] + s_sum[lrA][2] + s_sum[lrA][3];
        float tqA = s_sq[lrA][0] + s_sq[lrA][1] + s_sq[lrA][2] + s_sq[lrA][3];
        float tsB = s_sum[lrB][0] + s_sum[lrB][1] + s_sum[lrB][2] + s_sum[lrB][3];
        float tqB = s_sq[lrB][0] + s_sq[lrB][1] + s_sq[lrB][2] + s_sq[lrB][3];
        const float mA = tsA * (1.f / 256.f);
        const float rA = rsqrtf(tqA * (1.f / 256.f) - mA * mA + LN_EPS);
        const float mB = tsB * (1.f / 256.f);
        const float rB = rsqrtf(tqB * (1.f / 256.f) - mB * mB + LN_EPS);
#pragma unroll
        for (int nt = 0; nt < 8; nt++) {
            const int col = wn + nt * 8 + tg * 2;
            float2 vA = make_float2((acc[mt][nt][0] - mA) * rA,
                                    (acc[mt][nt][1] - mA) * rA);
            float2 vB = make_float2((acc[mt][nt][2] - mB) * rB,
                                    (acc[mt][nt][3] - mB) * rB);
            *(float2*)&outp[(size_t)(m0 + lrA) * 256 + col] = vA;
            *(float2*)&outp[(size_t)(m0 + lrB) * 256 + col] = vB;
        }
    }
}

// ---------------------------------------------------------------------------
extern "C" void kernel_launch(void* const* d_in, const int* in_sizes, int n_in,
                              void* d_out, int out_size) {
    const int*   seq   = (const int*)  d_in[0];
    const float* emb_w = (const float*)d_in[1];
    const float* emb_b = (const float*)d_in[2];
    const float* inp_w = (const float*)d_in[3];
    const float* inp_b = (const float*)d_in[4];
    const float* out_w = (const float*)d_in[5];
    const float* out_b = (const float*)d_in[6];
    float* out = (float*)d_out;

    uint32_t *p_embh, *p_qkvh, *p_ctxh, *p_wqkvh, *p_wouth;
    cudaGetSymbolAddress((void**)&p_embh, g_embh);
    cudaGetSymbolAddress((void**)&p_qkvh, g_qkvh);
    cudaGetSymbolAddress((void**)&p_ctxh, g_ctxh);
    cudaGetSymbolAddress((void**)&p_wqkvh, g_wqkvh);
    cudaGetSymbolAddress((void**)&p_wouth, g_wouth);

    const int gemm_smem = GEMM_SMEM_WORDS * 4;   // 73728
    const int op_smem = OP_SMEM_WORDS * 4;       // 92160
    cudaFuncSetAttribute(gemm_qkv_kernel,
                         cudaFuncAttributeMaxDynamicSharedMemorySize, gemm_smem);
    cudaFuncSetAttribute(attn_kernel,
                         cudaFuncAttributeMaxDynamicSharedMemorySize, ATTN_SMEM_BYTES);
    cudaFuncSetAttribute(outproj_ln_kernel,
                         cudaFuncAttributeMaxDynamicSharedMemorySize, op_smem);

    // 0. weight conversion fp32 -> fp16x2 (both matrices, one launch)
    cvtw_kernel<<<(NW1 + NW2 + 255) / 256, 256>>>(inp_w, out_w, p_wqkvh, p_wouth);
    // 1. embedding + LN (fp32 residual + fp16 copy), warp per row
    embed_ln_kernel<<<(NB * NL) / 8, 256>>>(seq, emb_w, emb_b);
    // 2. QKV projection -> packed fp16, Q pre-scaled by SC2F
    gemm_qkv_kernel<<<dim3(NE3 / 128, (NB * NL) / 128), 256, gemm_smem>>>(
        p_embh, p_wqkvh, inp_b, p_qkvh);
    // 3. fused flash attention -> g_ctxh (fp16)
    attn_kernel<<<dim3(NL / 128, NH, NB), 256, ATTN_SMEM_BYTES>>>();
    // 4. out-projection + residual + LN -> d_out
    outproj_ln_kernel<<<(NB * NL) / 64, 256, op_smem>>>(
        p_ctxh, p_wouth, out_b, out);
}

// round 11
// speedup vs baseline: 1.0482x; 1.0482x over previous
#include <cuda_runtime.h>
#include <math.h>
#include <cstdint>

#define NB 16
#define NL 1024
#define NC 4
#define NE 256
#define NH 8
#define NE3 768
#define LN_EPS 1e-5f
// (1/sqrt(32)) * log2(e): exp2-domain softmax scale, folded into Q in the GEMM
#define SC2F 0.25506298365213554f

// Scratch (static device globals — no dynamic allocation allowed)
__device__ __align__(16) float    g_emb[NB * NL * NE];        // fp32 residual
__device__ __align__(16) uint32_t g_embh[NB * NL * NE / 2];   // fp16x2 LN output
__device__ __align__(16) uint32_t g_qkvh[NB * NL * NE3 / 2];  // fp16x2 qkv (q pre-scaled)
__device__ __align__(16) uint32_t g_ctxh[NB * NL * NE / 2];   // fp16x2 context
__device__ __align__(16) uint32_t g_wqkvh[NE3 * NE / 2];      // in_proj_w fp16x2
__device__ __align__(16) uint32_t g_wouth[NE * NE / 2];       // out_w fp16x2

// ---------------------------------------------------------------------------
// PTX helpers (plain ISA only — ptxas targets sm_103 without 'a' features)
// ---------------------------------------------------------------------------
#define MMA_F16(c, a, b)                                                       \
    asm volatile("mma.sync.aligned.m16n8k16.row.col.f32.f16.f16.f32 "          \
        "{%0,%1,%2,%3}, {%4,%5,%6,%7}, {%8,%9}, {%0,%1,%2,%3};"                \
        : "+f"((c)[0]), "+f"((c)[1]), "+f"((c)[2]), "+f"((c)[3])               \
        : "r"((a)[0]), "r"((a)[1]), "r"((a)[2]), "r"((a)[3]),                  \
          "r"((b)[0]), "r"((b)[1]))

#define PACKF16(r, lo, hi)                                                     \
    asm("cvt.rn.f16x2.f32 %0, %1, %2;" : "=r"(r) : "f"(hi), "f"(lo))

// two fp16 exp2 in ONE MUFU op (halves MUFU pressure vs exp2f)
#define EX2H2(r) asm("ex2.approx.f16x2 %0, %0;" : "+r"(r))

#define CP_ASYNC16(dst_u32, src_ptr)                                           \
    asm volatile("cp.async.cg.shared.global [%0], [%1], 16;"                   \
                 :: "r"(dst_u32), "l"(src_ptr))
#define CP_COMMIT() asm volatile("cp.async.commit_group;" ::: "memory")
#define CP_WAIT1()  asm volatile("cp.async.wait_group 1;" ::: "memory")
#define CP_WAIT0()  asm volatile("cp.async.wait_group 0;" ::: "memory")

#define LDSM4(r0, r1, r2, r3, addr)                                            \
    asm volatile("ldmatrix.sync.aligned.m8n8.x4.shared.b16 {%0,%1,%2,%3}, [%4];" \
        : "=r"(r0), "=r"(r1), "=r"(r2), "=r"(r3) : "r"(addr))
#define LDSM4T(r0, r1, r2, r3, addr)                                           \
    asm volatile("ldmatrix.sync.aligned.m8n8.x4.trans.shared.b16 {%0,%1,%2,%3}, [%4];" \
        : "=r"(r0), "=r"(r1), "=r"(r2), "=r"(r3) : "r"(addr))

// ---------------------------------------------------------------------------
// Kernel 0: fp32 -> packed fp16x2 conversion of BOTH weight matrices (1 launch)
// ---------------------------------------------------------------------------
#define NW1 (NE3 * NE / 2)
#define NW2 (NE * NE / 2)
__global__ void cvtw_kernel(const float* __restrict__ src1,
                            const float* __restrict__ src2,
                            uint32_t* __restrict__ dst1,
                            uint32_t* __restrict__ dst2) {
    int i = blockIdx.x * 256 + threadIdx.x;
    if (i < NW1) {
        uint32_t w;
        PACKF16(w, src1[2 * i], src1[2 * i + 1]);
        dst1[i] = w;
    } else {
        int j = i - NW1;
        if (j < NW2) {
            uint32_t w;
            PACKF16(w, src2[2 * j], src2[2 * j + 1]);
            dst2[j] = w;
        }
    }
}

// ---------------------------------------------------------------------------
// Kernel 1: embedding gather + bias + LayerNorm.  Warp per row (8 rows/block):
// warp-shuffle reduction only — no barrier, no smem.
// ---------------------------------------------------------------------------
__global__ void __launch_bounds__(256) embed_ln_kernel(
    const int* __restrict__ seq, const float* __restrict__ emb_w,
    const float* __restrict__ emb_b) {
    const int wid = threadIdx.x >> 5, lane = threadIdx.x & 31;
    const int row = blockIdx.x * 8 + wid;
    const int l = row & (NL - 1);
    const int c = seq[row];

    float v[8];
    float s = 0.f, q = 0.f;
#pragma unroll
    for (int i = 0; i < 8; i++) {
        const int e = lane + 32 * i;
        v[i] = emb_w[(l * NE + e) * NC + c] + emb_b[l * NE + e];
        s += v[i];
        q += v[i] * v[i];
    }
#pragma unroll
    for (int o = 16; o > 0; o >>= 1) {
        s += __shfl_xor_sync(0xffffffffu, s, o);
        q += __shfl_xor_sync(0xffffffffu, q, o);
    }
    const float mean = s * (1.f / NE);
    const float var = q * (1.f / NE) - mean * mean;
    const float r = rsqrtf(var + LN_EPS);
#pragma unroll
    for (int i = 0; i < 8; i++) {
        const int e = lane + 32 * i;
        const float y = (v[i] - mean) * r;
        g_emb[(size_t)row * NE + e] = y;
        const float y1 = __shfl_down_sync(0xffffffffu, y, 1);
        if ((lane & 1) == 0) {
            uint32_t w;
            PACKF16(w, y, y1);
            g_embh[(size_t)row * (NE / 2) + (e >> 1)] = w;
        }
    }
}

// ---------------------------------------------------------------------------
// Kernel 2: QKV fp16 GEMM.  Block tile 128x128, 8 warps (4m x 2n) of 32x64.
// Single barrier per K-chunk: wait -> sync -> issue(next) -> compute.
// Q columns (col<256) scaled by SC2F in epilogue (exp2-domain softmax).
// ---------------------------------------------------------------------------
#define GEMM_SMEM_WORDS (4 * 4608)     // As[2][128][36] + Bs[2][128][36]

__global__ void __launch_bounds__(256) gemm_qkv_kernel(
    const uint32_t* __restrict__ A, const uint32_t* __restrict__ W,
    const float* __restrict__ bias, uint32_t* __restrict__ C16) {
    extern __shared__ uint32_t sm[];
    const int tid = threadIdx.x, wid = tid >> 5, lane = tid & 31;
    const int g = lane >> 2, tg = lane & 3;
    const int m0 = blockIdx.y * 128, n0 = blockIdx.x * 128;
    const int wm = (wid & 3) * 32, wn = (wid >> 2) * 64;
    const uint32_t smb = (uint32_t)__cvta_generic_to_shared(sm);
    const int a_r = lane & 15, a_c = (lane >> 4) * 4;
    const int b_r = (lane & 7) + ((lane >> 4) << 3), b_c = ((lane >> 3) & 1) * 4;

    float acc[2][8][4];
#pragma unroll
    for (int mt = 0; mt < 2; mt++)
#pragma unroll
        for (int nt = 0; nt < 8; nt++)
#pragma unroll
            for (int j = 0; j < 4; j++) acc[mt][nt][j] = 0.f;

#define QKV_ISSUE(cc)                                                          \
    do {                                                                       \
        const int _s = (cc) & 1;                                               \
        _Pragma("unroll")                                                      \
        for (int it = 0; it < 4; it++) {                                       \
            int t = tid + it * 256;                                            \
            int r = t >> 3, c = (t & 7) * 4;                                   \
            CP_ASYNC16(smb + (uint32_t)(_s * 4608 + r * 36 + c) * 4,           \
                       &A[(size_t)(m0 + r) * 128 + (cc) * 32 + c]);            \
        }                                                                      \
        _Pragma("unroll")                                                      \
        for (int it = 0; it < 4; it++) {                                       \
            int t = tid + it * 256;                                            \
            int r = t >> 3, c = (t & 7) * 4;                                   \
            CP_ASYNC16(smb + (uint32_t)(9216 + _s * 4608 + r * 36 + c) * 4,    \
                       &W[(size_t)(n0 + r) * 128 + (cc) * 32 + c]);            \
        }                                                                      \
    } while (0)

    QKV_ISSUE(0);
    CP_COMMIT();

#pragma unroll
    for (int cchunk = 0; cchunk < 4; cchunk++) {
        CP_WAIT0();
        __syncthreads();            // buffer 'cchunk' visible; stale buffer free
        if (cchunk < 3) {
            QKV_ISSUE(cchunk + 1);
            CP_COMMIT();
        }
        const uint32_t abase = smb + (uint32_t)((cchunk & 1) * 4608) * 4;
        const uint32_t bbase = smb + (uint32_t)(9216 + (cchunk & 1) * 4608) * 4;
#pragma unroll
        for (int ks = 0; ks < 4; ks++) {
            const int k0 = ks * 8;
            uint32_t af[2][4];
#pragma unroll
            for (int mt = 0; mt < 2; mt++)
                LDSM4(af[mt][0], af[mt][1], af[mt][2], af[mt][3],
                      abase + (uint32_t)((wm + mt * 16 + a_r) * 36 + k0 + a_c) * 4);
            uint32_t bf[8][2];
#pragma unroll
            for (int ntp = 0; ntp < 4; ntp++)
                LDSM4(bf[2 * ntp][0], bf[2 * ntp][1], bf[2 * ntp + 1][0], bf[2 * ntp + 1][1],
                      bbase + (uint32_t)((wn + ntp * 16 + b_r) * 36 + k0 + b_c) * 4);
#pragma unroll
            for (int mt = 0; mt < 2; mt++)
#pragma unroll
                for (int nt = 0; nt < 8; nt++)
                    MMA_F16(acc[mt][nt], af[mt], bf[nt]);
        }
    }
#undef QKV_ISSUE

#pragma unroll
    for (int mt = 0; mt < 2; mt++)
#pragma unroll
        for (int nt = 0; nt < 8; nt++) {
            const int row = m0 + wm + mt * 16 + g;
            const int col = n0 + wn + nt * 8 + tg * 2;
            const float scl = (col < 256) ? SC2F : 1.0f;  // Q gets softmax scale
            const float b0 = bias[col], b1 = bias[col + 1];
            const int colw = col >> 1;
            uint32_t w0, w1;
            PACKF16(w0, (acc[mt][nt][0] + b0) * scl, (acc[mt][nt][1] + b1) * scl);
            PACKF16(w1, (acc[mt][nt][2] + b0) * scl, (acc[mt][nt][3] + b1) * scl);
            C16[(size_t)row * 384 + colw] = w0;
            C16[(size_t)(row + 8) * 384 + colw] = w1;
        }
}

// ---------------------------------------------------------------------------
// Kernel 3: fused flash attention (R9 shape: 64-key chunks, 40KB static smem,
// triple buffer) with __launch_bounds__(256, 5): ptxas caps regs at 51 so
// 5 CTAs/SM fit (reg file), raising resident warps 25% to fill the softmax
// bubbles on the tensor pipe.  fp16 MMA; no-max exp2 softmax (ex2.approx.f16x2);
// row-sum l via MMA against all-ones B; Q frags hoisted.
// ---------------------------------------------------------------------------
__global__ void __launch_bounds__(256, 5) attn_kernel() {
    const int qb = blockIdx.x * 128;
    const int h  = blockIdx.y;
    const int b  = blockIdx.z;
    const int tid = threadIdx.x, wid = tid >> 5, lane = tid & 31;
    const int g = lane >> 2, tg = lane & 3;
    const int qw = wid * 16;

    __shared__ uint32_t Qs[128][20];     // f16x2, [q][d/2]
    __shared__ uint32_t Ks[3][64][20];   // f16x2, triple buffered
    __shared__ uint32_t Vs[3][64][20];

    const uint32_t smQ = (uint32_t)__cvta_generic_to_shared(Qs);
    const uint32_t smK = (uint32_t)__cvta_generic_to_shared(Ks);
    const uint32_t smV = (uint32_t)__cvta_generic_to_shared(Vs);

#pragma unroll
    for (int it = 0; it < 2; it++) {
        int t = tid + it * 256;
        int r = t >> 2, c4 = (t & 3) * 4;
        *(uint4*)&Qs[r][c4] =
            *(const uint4*)&g_qkvh[(size_t)(b * NL + qb + r) * 384 + h * 16 + c4];
    }

    const uint32_t q_ad = smQ + (uint32_t)((qw + (lane & 15)) * 20 + ((lane >> 4) << 2)) * 4;
    const uint32_t k_ad = smK + (uint32_t)(((lane & 7) + ((lane >> 4) << 3)) * 20 +
                                           (((lane >> 3) & 1) << 2)) * 4;
    const uint32_t v_ad = smV + (uint32_t)((lane & 15) * 20 + ((lane >> 4) << 2)) * 4;

    float o[4][4], lacc[4];
#pragma unroll
    for (int nt = 0; nt < 4; nt++)
#pragma unroll
        for (int j = 0; j < 4; j++) o[nt][j] = 0.f;
#pragma unroll
    for (int j = 0; j < 4; j++) lacc[j] = 0.f;
    const uint32_t ones2[2] = {0x3C003C00u, 0x3C003C00u};  // fp16 1.0 x2

    const int fr = tid >> 2, fc4 = (tid & 3) * 4;

#define ATTN_ISSUE(kb, buf)                                                    \
    do {                                                                       \
        size_t base = (size_t)(b * NL + (kb) + fr) * 384 + h * 16 + fc4;       \
        uint32_t off = (uint32_t)((buf) * 1280 + fr * 20 + fc4) * 4;           \
        CP_ASYNC16(smK + off, &g_qkvh[base + 128]);                            \
        CP_ASYNC16(smV + off, &g_qkvh[base + 256]);                            \
    } while (0)

    ATTN_ISSUE(0, 0);
    CP_COMMIT();
    ATTN_ISSUE(64, 1);
    CP_COMMIT();
    __syncthreads();               // Qs visible -> load Q fragments once

    uint32_t qf[2][4];
#pragma unroll
    for (int ks = 0; ks < 2; ks++)
        LDSM4(qf[ks][0], qf[ks][1], qf[ks][2], qf[ks][3], q_ad + ks * 32);

    int buf = 0;
#pragma unroll 1
    for (int it = 0; it < 16; it++) {
        if (it >= 14) CP_WAIT0(); else CP_WAIT1();
        __syncthreads();           // buffer 'it' visible; buffer (it-1)%3 free
        if (it < 14) {
            ATTN_ISSUE((it + 2) * 64, (buf + 2) % 3);
            CP_COMMIT();
        }
        const uint32_t boff = (uint32_t)(buf * 5120);

        // ---- S = Q K^T : 8 n-tiles of 8 keys, 2 k16 steps ----
        float s[8][4];
#pragma unroll
        for (int nt = 0; nt < 8; nt++)
#pragma unroll
            for (int j = 0; j < 4; j++) s[nt][j] = 0.f;
#pragma unroll
        for (int ks = 0; ks < 2; ks++) {
#pragma unroll
            for (int ntp = 0; ntp < 4; ntp++) {
                uint32_t b0, b1, b2, b3;
                LDSM4(b0, b1, b2, b3, k_ad + boff + ntp * 1280 + ks * 32);
                uint32_t bfa[2] = {b0, b1};
                uint32_t bfb[2] = {b2, b3};
                MMA_F16(s[2 * ntp], qf[ks], bfa);
                MMA_F16(s[2 * ntp + 1], qf[ks], bfb);
            }
        }

        // ---- pack to fp16 pairs, then p = exp2 via f16x2 MUFU (2 per op) ----
        uint32_t p[8][2];
#pragma unroll
        for (int nt = 0; nt < 8; nt++) {
            PACKF16(p[nt][0], s[nt][0], s[nt][1]);   // row g
            PACKF16(p[nt][1], s[nt][2], s[nt][3]);   // row g+8
            EX2H2(p[nt][0]);
            EX2H2(p[nt][1]);
        }

        // ---- O += P V  and  l += P @ ones (row sum via MMA, no shuffles) ----
#pragma unroll
        for (int ks = 0; ks < 4; ks++) {          // 16 keys per step
            uint32_t ap[4] = {p[2 * ks][0], p[2 * ks][1],
                              p[2 * ks + 1][0], p[2 * ks + 1][1]};
            MMA_F16(lacc, ap, ones2);
#pragma unroll
            for (int ntp = 0; ntp < 2; ntp++) {
                uint32_t b0, b1, b2, b3;
                LDSM4T(b0, b1, b2, b3, v_ad + boff + ks * 1280 + ntp * 32);
                uint32_t bfa[2] = {b0, b1};
                uint32_t bfb[2] = {b2, b3};
                MMA_F16(o[2 * ntp], ap, bfa);
                MMA_F16(o[2 * ntp + 1], ap, bfb);
            }
        }
        buf = (buf + 1) % 3;
    }
#undef ATTN_ISSUE

    // lacc[0] = full row-g sum, lacc[2] = full row-(g+8) sum (all lanes agree)
    const float inv0 = 1.f / lacc[0];
    const float inv1 = 1.f / lacc[2];
    const int row = b * NL + qb + qw + g;
#pragma unroll
    for (int nt = 0; nt < 4; nt++) {
        const int colw = h * 16 + nt * 4 + tg;
        uint32_t w0, w1;
        PACKF16(w0, o[nt][0] * inv0, o[nt][1] * inv0);
        PACKF16(w1, o[nt][2] * inv1, o[nt][3] * inv1);
        g_ctxh[(size_t)row * 128 + colw] = w0;
        g_ctxh[(size_t)(row + 8) * 128 + colw] = w1;
    }
}

// ---------------------------------------------------------------------------
// Kernel 4: fused out-projection + residual + LayerNorm -> d_out.
// Block tile 64x256 (full rows), 8 warps (2m x 4n) of 32x64; K = 256.
// Single barrier per K-chunk.
// ---------------------------------------------------------------------------
#define OP_SMEM_WORDS (2 * 2304 + 2 * 9216)

__global__ void __launch_bounds__(256) outproj_ln_kernel(
    const uint32_t* __restrict__ Ctx, const uint32_t* __restrict__ Wh,
    const float* __restrict__ bias, float* __restrict__ outp) {
    extern __shared__ uint32_t sm[];
    __shared__ float s_sum[64][4], s_sq[64][4];
    const int tid = threadIdx.x, wid = tid >> 5, lane = tid & 31;
    const int g = lane >> 2, tg = lane & 3;
    const int m0 = blockIdx.x * 64;
    const int wm = (wid & 1) * 32, wn = (wid >> 1) * 64, nw = wid >> 1;
    const uint32_t smb = (uint32_t)__cvta_generic_to_shared(sm);
    const int a_r = lane & 15, a_c = (lane >> 4) * 4;
    const int b_r = (lane & 7) + ((lane >> 4) << 3), b_c = ((lane >> 3) & 1) * 4;

    float acc[2][8][4];
#pragma unroll
    for (int mt = 0; mt < 2; mt++)
#pragma unroll
        for (int nt = 0; nt < 8; nt++)
#pragma unroll
            for (int j = 0; j < 4; j++) acc[mt][nt][j] = 0.f;

#define OP_ISSUE(cc)                                                           \
    do {                                                                       \
        const int _s = (cc) & 1;                                               \
        _Pragma("unroll")                                                      \
        for (int it = 0; it < 2; it++) {                                       \
            int t = tid + it * 256;                                            \
            int r = t >> 3, c = (t & 7) * 4;                                   \
            CP_ASYNC16(smb + (uint32_t)(_s * 2304 + r * 36 + c) * 4,           \
                       &Ctx[(size_t)(m0 + r) * 128 + (cc) * 32 + c]);          \
        }                                                                      \
        _Pragma("unroll")                                                      \
        for (int it = 0; it < 8; it++) {                                       \
            int t = tid + it * 256;                                            \
            int r = t >> 3, c = (t & 7) * 4;                                   \
            CP_ASYNC16(smb + (uint32_t)(4608 + _s * 9216 + r * 36 + c) * 4,    \
                       &Wh[(size_t)r * 128 + (cc) * 32 + c]);                  \
        }                                                                      \
    } while (0)

    OP_ISSUE(0);
    CP_COMMIT();

#pragma unroll
    for (int cchunk = 0; cchunk < 4; cchunk++) {
        CP_WAIT0();
        __syncthreads();
        if (cchunk < 3) {
            OP_ISSUE(cchunk + 1);
            CP_COMMIT();
        }
        const uint32_t abase = smb + (uint32_t)((cchunk & 1) * 2304) * 4;
        const uint32_t bbase = smb + (uint32_t)(4608 + (cchunk & 1) * 9216) * 4;
#pragma unroll
        for (int ks = 0; ks < 4; ks++) {
            const int k0 = ks * 8;
            uint32_t af[2][4];
#pragma unroll
            for (int mt = 0; mt < 2; mt++)
                LDSM4(af[mt][0], af[mt][1], af[mt][2], af[mt][3],
                      abase + (uint32_t)((wm + mt * 16 + a_r) * 36 + k0 + a_c) * 4);
            uint32_t bf[8][2];
#pragma unroll
            for (int ntp = 0; ntp < 4; ntp++)
                LDSM4(bf[2 * ntp][0], bf[2 * ntp][1], bf[2 * ntp + 1][0], bf[2 * ntp + 1][1],
                      bbase + (uint32_t)((wn + ntp * 16 + b_r) * 36 + k0 + b_c) * 4);
#pragma unroll
            for (int mt = 0; mt < 2; mt++)
#pragma unroll
                for (int nt = 0; nt < 8; nt++)
                    MMA_F16(acc[mt][nt], af[mt], bf[nt]);
        }
    }
#undef OP_ISSUE

#pragma unroll
    for (int mt = 0; mt < 2; mt++)
#pragma unroll
        for (int nt = 0; nt < 8; nt++) {
            const int col = wn + nt * 8 + tg * 2;
            const int rA = m0 + wm + mt * 16 + g;
            const float b0 = bias[col], b1 = bias[col + 1];
            float2 eA = *(const float2*)&g_emb[(size_t)rA * 256 + col];
            float2 eB = *(const float2*)&g_emb[(size_t)(rA + 8) * 256 + col];
            acc[mt][nt][0] += b0 + eA.x;
            acc[mt][nt][1] += b1 + eA.y;
            acc[mt][nt][2] += b0 + eB.x;
            acc[mt][nt][3] += b1 + eB.y;
        }

#pragma unroll
    for (int mt = 0; mt < 2; mt++) {
        float sA = 0.f, qA = 0.f, sB = 0.f, qB = 0.f;
#pragma unroll
        for (int nt = 0; nt < 8; nt++) {
            sA += acc[mt][nt][0] + acc[mt][nt][1];
            qA += acc[mt][nt][0] * acc[mt][nt][0] + acc[mt][nt][1] * acc[mt][nt][1];
            sB += acc[mt][nt][2] + acc[mt][nt][3];
            qB += acc[mt][nt][2] * acc[mt][nt][2] + acc[mt][nt][3] * acc[mt][nt][3];
        }
#pragma unroll
        for (int off = 1; off < 4; off <<= 1) {
            sA += __shfl_xor_sync(0xffffffffu, sA, off);
            qA += __shfl_xor_sync(0xffffffffu, qA, off);
            sB += __shfl_xor_sync(0xffffffffu, sB, off);
            qB += __shfl_xor_sync(0xffffffffu, qB, off);
        }
        if (tg == 0) {
            const int lr = wm + mt * 16 + g;
            s_sum[lr][nw] = sA; s_sq[lr][nw] = qA;
            s_sum[lr + 8][nw] = sB; s_sq[lr + 8][nw] = qB;
        }
    }
    __syncthreads();

#pragma unroll
    for (int mt = 0; mt < 2; mt++) {
        const int lrA = wm + mt * 16 + g, lrB = lrA + 8;
        float tsA = s_sum[lrA][0] + s_sum[lrA][1] + s_sum[lrA][2] + s_sum[lrA][3];
        float tqA = s_sq[lrA][0] + s_sq[lrA][1] + s_sq[lrA][2] + s_sq[lrA][3];
        float tsB = s_sum[lrB][0] + s_sum[lrB][1] + s_sum[lrB][2] + s_sum[lrB][3];
        float tqB = s_sq[lrB][0] + s_sq[lrB][1] + s_sq[lrB][2] + s_sq[lrB][3];
        const float mA = tsA * (1.f / 256.f);
        const float rA = rsqrtf(tqA * (1.f / 256.f) - mA * mA + LN_EPS);
        const float mB = tsB * (1.f / 256.f);
        const float rB = rsqrtf(tqB * (1.f / 256.f) - mB * mB + LN_EPS);
#pragma unroll
        for (int nt = 0; nt < 8; nt++) {
            const int col = wn + nt * 8 + tg * 2;
            float2 vA = make_float2((acc[mt][nt][0] - mA) * rA,
                                    (acc[mt][nt][1] - mA) * rA);
            float2 vB = make_float2((acc[mt][nt][2] - mB) * rB,
                                    (acc[mt][nt][3] - mB) * rB);
            *(float2*)&outp[(size_t)(m0 + lrA) * 256 + col] = vA;
            *(float2*)&outp[(size_t)(m0 + lrB) * 256 + col] = vB;
        }
    }
}

// ---------------------------------------------------------------------------
extern "C" void kernel_launch(void* const* d_in, const int* in_sizes, int n_in,
                              void* d_out, int out_size) {
    const int*   seq   = (const int*)  d_in[0];
    const float* emb_w = (const float*)d_in[1];
    const float* emb_b = (const float*)d_in[2];
    const float* inp_w = (const float*)d_in[3];
    const float* inp_b = (const float*)d_in[4];
    const float* out_w = (const float*)d_in[5];
    const float* out_b = (const float*)d_in[6];
    float* out = (float*)d_out;

    uint32_t *p_embh, *p_qkvh, *p_ctxh, *p_wqkvh, *p_wouth;
    cudaGetSymbolAddress((void**)&p_embh, g_embh);
    cudaGetSymbolAddress((void**)&p_qkvh, g_qkvh);
    cudaGetSymbolAddress((void**)&p_ctxh, g_ctxh);
    cudaGetSymbolAddress((void**)&p_wqkvh, g_wqkvh);
    cudaGetSymbolAddress((void**)&p_wouth, g_wouth);

    const int gemm_smem = GEMM_SMEM_WORDS * 4;   // 73728
    const int op_smem = OP_SMEM_WORDS * 4;       // 92160
    cudaFuncSetAttribute(gemm_qkv_kernel,
                         cudaFuncAttributeMaxDynamicSharedMemorySize, gemm_smem);
    cudaFuncSetAttribute(outproj_ln_kernel,
                         cudaFuncAttributeMaxDynamicSharedMemorySize, op_smem);

    // 0. weight conversion fp32 -> fp16x2 (both matrices, one launch)
    cvtw_kernel<<<(NW1 + NW2 + 255) / 256, 256>>>(inp_w, out_w, p_wqkvh, p_wouth);
    // 1. embedding + LN (fp32 residual + fp16 copy), warp per row
    embed_ln_kernel<<<(NB * NL) / 8, 256>>>(seq, emb_w, emb_b);
    // 2. QKV projection -> packed fp16, Q pre-scaled by SC2F
    gemm_qkv_kernel<<<dim3(NE3 / 128, (NB * NL) / 128), 256, gemm_smem>>>(
        p_embh, p_wqkvh, inp_b, p_qkvh);
    // 3. fused flash attention -> g_ctxh (fp16)
    attn_kernel<<<dim3(NL / 128, NH, NB), 256>>>();
    // 4. out-projection + residual + LN -> d_out
    outproj_ln_kernel<<<(NB * NL) / 64, 256, op_smem>>>(
        p_ctxh, p_wouth, out_b, out);
}

// round 12
// speedup vs baseline: 1.0516x; 1.0032x over previous
#include <cuda_runtime.h>
#include <math.h>
#include <cstdint>

#define NB 16
#define NL 1024
#define NC 4
#define NE 256
#define NH 8
#define NE3 768
#define LN_EPS 1e-5f
// (1/sqrt(32)) * log2(e): exp2-domain softmax scale, folded into Q in the GEMM
#define SC2F 0.25506298365213554f

// Scratch (static device globals — no dynamic allocation allowed)
__device__ __align__(16) float    g_emb[NB * NL * NE];        // fp32 residual
__device__ __align__(16) uint32_t g_embh[NB * NL * NE / 2];   // fp16x2 LN output
__device__ __align__(16) uint32_t g_qkvh[NB * NL * NE3 / 2];  // fp16x2 qkv (q pre-scaled)
__device__ __align__(16) uint32_t g_ctxh[NB * NL * NE / 2];   // fp16x2 context
__device__ __align__(16) uint32_t g_wqkvh[NE3 * NE / 2];      // in_proj_w fp16x2
__device__ __align__(16) uint32_t g_wouth[NE * NE / 2];       // out_w fp16x2

// ---------------------------------------------------------------------------
// PTX helpers (plain ISA only — ptxas targets sm_103 without 'a' features)
// ---------------------------------------------------------------------------
#define MMA_F16(c, a, b)                                                       \
    asm volatile("mma.sync.aligned.m16n8k16.row.col.f32.f16.f16.f32 "          \
        "{%0,%1,%2,%3}, {%4,%5,%6,%7}, {%8,%9}, {%0,%1,%2,%3};"                \
        : "+f"((c)[0]), "+f"((c)[1]), "+f"((c)[2]), "+f"((c)[3])               \
        : "r"((a)[0]), "r"((a)[1]), "r"((a)[2]), "r"((a)[3]),                  \
          "r"((b)[0]), "r"((b)[1]))

#define PACKF16(r, lo, hi)                                                     \
    asm("cvt.rn.f16x2.f32 %0, %1, %2;" : "=r"(r) : "f"(hi), "f"(lo))

// two fp16 exp2 in ONE MUFU op (halves MUFU pressure vs exp2f)
#define EX2H2(r) asm("ex2.approx.f16x2 %0, %0;" : "+r"(r))

#define CP_ASYNC16(dst_u32, src_ptr)                                           \
    asm volatile("cp.async.cg.shared.global [%0], [%1], 16;"                   \
                 :: "r"(dst_u32), "l"(src_ptr))
#define CP_COMMIT() asm volatile("cp.async.commit_group;" ::: "memory")
#define CP_WAIT1()  asm volatile("cp.async.wait_group 1;" ::: "memory")
#define CP_WAIT0()  asm volatile("cp.async.wait_group 0;" ::: "memory")

#define LDSM4(r0, r1, r2, r3, addr)                                            \
    asm volatile("ldmatrix.sync.aligned.m8n8.x4.shared.b16 {%0,%1,%2,%3}, [%4];" \
        : "=r"(r0), "=r"(r1), "=r"(r2), "=r"(r3) : "r"(addr))
#define LDSM4T(r0, r1, r2, r3, addr)                                           \
    asm volatile("ldmatrix.sync.aligned.m8n8.x4.trans.shared.b16 {%0,%1,%2,%3}, [%4];" \
        : "=r"(r0), "=r"(r1), "=r"(r2), "=r"(r3) : "r"(addr))

// ---------------------------------------------------------------------------
// Kernel 0: fp32 -> packed fp16x2 conversion of BOTH weight matrices (1 launch)
// ---------------------------------------------------------------------------
#define NW1 (NE3 * NE / 2)
#define NW2 (NE * NE / 2)
__global__ void cvtw_kernel(const float* __restrict__ src1,
                            const float* __restrict__ src2,
                            uint32_t* __restrict__ dst1,
                            uint32_t* __restrict__ dst2) {
    int i = blockIdx.x * 256 + threadIdx.x;
    if (i < NW1) {
        uint32_t w;
        PACKF16(w, src1[2 * i], src1[2 * i + 1]);
        dst1[i] = w;
    } else {
        int j = i - NW1;
        if (j < NW2) {
            uint32_t w;
            PACKF16(w, src2[2 * j], src2[2 * j + 1]);
            dst2[j] = w;
        }
    }
}

// ---------------------------------------------------------------------------
// Kernel 1: embedding gather + bias + LayerNorm.  Warp per row (8 rows/block):
// warp-shuffle reduction only — no barrier, no smem.
// ---------------------------------------------------------------------------
__global__ void __launch_bounds__(256) embed_ln_kernel(
    const int* __restrict__ seq, const float* __restrict__ emb_w,
    const float* __restrict__ emb_b) {
    const int wid = threadIdx.x >> 5, lane = threadIdx.x & 31;
    const int row = blockIdx.x * 8 + wid;
    const int l = row & (NL - 1);
    const int c = seq[row];

    float v[8];
    float s = 0.f, q = 0.f;
#pragma unroll
    for (int i = 0; i < 8; i++) {
        const int e = lane + 32 * i;
        v[i] = emb_w[(l * NE + e) * NC + c] + emb_b[l * NE + e];
        s += v[i];
        q += v[i] * v[i];
    }
#pragma unroll
    for (int o = 16; o > 0; o >>= 1) {
        s += __shfl_xor_sync(0xffffffffu, s, o);
        q += __shfl_xor_sync(0xffffffffu, q, o);
    }
    const float mean = s * (1.f / NE);
    const float var = q * (1.f / NE) - mean * mean;
    const float r = rsqrtf(var + LN_EPS);
#pragma unroll
    for (int i = 0; i < 8; i++) {
        const int e = lane + 32 * i;
        const float y = (v[i] - mean) * r;
        g_emb[(size_t)row * NE + e] = y;
        const float y1 = __shfl_down_sync(0xffffffffu, y, 1);
        if ((lane & 1) == 0) {
            uint32_t w;
            PACKF16(w, y, y1);
            g_embh[(size_t)row * (NE / 2) + (e >> 1)] = w;
        }
    }
}

// ---------------------------------------------------------------------------
// Kernel 2: QKV fp16 GEMM.  Block tile 128x128, 8 warps (4m x 2n) of 32x64.
// Single barrier per K-chunk: wait -> sync -> issue(next) -> compute.
// Q columns (col<256) scaled by SC2F in epilogue (exp2-domain softmax).
// ---------------------------------------------------------------------------
#define GEMM_SMEM_WORDS (4 * 4608)     // As[2][128][36] + Bs[2][128][36]

__global__ void __launch_bounds__(256) gemm_qkv_kernel(
    const uint32_t* __restrict__ A, const uint32_t* __restrict__ W,
    const float* __restrict__ bias, uint32_t* __restrict__ C16) {
    extern __shared__ uint32_t sm[];
    const int tid = threadIdx.x, wid = tid >> 5, lane = tid & 31;
    const int g = lane >> 2, tg = lane & 3;
    const int m0 = blockIdx.y * 128, n0 = blockIdx.x * 128;
    const int wm = (wid & 3) * 32, wn = (wid >> 2) * 64;
    const uint32_t smb = (uint32_t)__cvta_generic_to_shared(sm);
    const int a_r = lane & 15, a_c = (lane >> 4) * 4;
    const int b_r = (lane & 7) + ((lane >> 4) << 3), b_c = ((lane >> 3) & 1) * 4;

    float acc[2][8][4];
#pragma unroll
    for (int mt = 0; mt < 2; mt++)
#pragma unroll
        for (int nt = 0; nt < 8; nt++)
#pragma unroll
            for (int j = 0; j < 4; j++) acc[mt][nt][j] = 0.f;

#define QKV_ISSUE(cc)                                                          \
    do {                                                                       \
        const int _s = (cc) & 1;                                               \
        _Pragma("unroll")                                                      \
        for (int it = 0; it < 4; it++) {                                       \
            int t = tid + it * 256;                                            \
            int r = t >> 3, c = (t & 7) * 4;                                   \
            CP_ASYNC16(smb + (uint32_t)(_s * 4608 + r * 36 + c) * 4,           \
                       &A[(size_t)(m0 + r) * 128 + (cc) * 32 + c]);            \
        }                                                                      \
        _Pragma("unroll")                                                      \
        for (int it = 0; it < 4; it++) {                                       \
            int t = tid + it * 256;                                            \
            int r = t >> 3, c = (t & 7) * 4;                                   \
            CP_ASYNC16(smb + (uint32_t)(9216 + _s * 4608 + r * 36 + c) * 4,    \
                       &W[(size_t)(n0 + r) * 128 + (cc) * 32 + c]);            \
        }                                                                      \
    } while (0)

    QKV_ISSUE(0);
    CP_COMMIT();

#pragma unroll
    for (int cchunk = 0; cchunk < 4; cchunk++) {
        CP_WAIT0();
        __syncthreads();            // buffer 'cchunk' visible; stale buffer free
        if (cchunk < 3) {
            QKV_ISSUE(cchunk + 1);
            CP_COMMIT();
        }
        const uint32_t abase = smb + (uint32_t)((cchunk & 1) * 4608) * 4;
        const uint32_t bbase = smb + (uint32_t)(9216 + (cchunk & 1) * 4608) * 4;
#pragma unroll
        for (int ks = 0; ks < 4; ks++) {
            const int k0 = ks * 8;
            uint32_t af[2][4];
#pragma unroll
            for (int mt = 0; mt < 2; mt++)
                LDSM4(af[mt][0], af[mt][1], af[mt][2], af[mt][3],
                      abase + (uint32_t)((wm + mt * 16 + a_r) * 36 + k0 + a_c) * 4);
            uint32_t bf[8][2];
#pragma unroll
            for (int ntp = 0; ntp < 4; ntp++)
                LDSM4(bf[2 * ntp][0], bf[2 * ntp][1], bf[2 * ntp + 1][0], bf[2 * ntp + 1][1],
                      bbase + (uint32_t)((wn + ntp * 16 + b_r) * 36 + k0 + b_c) * 4);
#pragma unroll
            for (int mt = 0; mt < 2; mt++)
#pragma unroll
                for (int nt = 0; nt < 8; nt++)
                    MMA_F16(acc[mt][nt], af[mt], bf[nt]);
        }
    }
#undef QKV_ISSUE

#pragma unroll
    for (int mt = 0; mt < 2; mt++)
#pragma unroll
        for (int nt = 0; nt < 8; nt++) {
            const int row = m0 + wm + mt * 16 + g;
            const int col = n0 + wn + nt * 8 + tg * 2;
            const float scl = (col < 256) ? SC2F : 1.0f;  // Q gets softmax scale
            const float b0 = bias[col], b1 = bias[col + 1];
            const int colw = col >> 1;
            uint32_t w0, w1;
            PACKF16(w0, (acc[mt][nt][0] + b0) * scl, (acc[mt][nt][1] + b1) * scl);
            PACKF16(w1, (acc[mt][nt][2] + b0) * scl, (acc[mt][nt][3] + b1) * scl);
            C16[(size_t)row * 384 + colw] = w0;
            C16[(size_t)(row + 8) * 384 + colw] = w1;
        }
}

// ---------------------------------------------------------------------------
// Kernel 3: fused flash attention.  64-key chunks, triple-buffered static
// smem (40KB), 5 CTAs/SM.  No-max exp2 softmax has NO cross-tile dependency,
// so S is consumed per 16-key tile-pair: MMA pair -> pack -> ex2.f16x2,
// keeping only 8 fp32 scores live (32 in R10/11) -> ~48 regs WITHOUT spills.
// Row-sum l via MMA against all-ones B; Q frags hoisted.
// ---------------------------------------------------------------------------
__global__ void __launch_bounds__(256, 5) attn_kernel() {
    const int qb = blockIdx.x * 128;
    const int h  = blockIdx.y;
    const int b  = blockIdx.z;
    const int tid = threadIdx.x, wid = tid >> 5, lane = tid & 31;
    const int g = lane >> 2, tg = lane & 3;
    const int qw = wid * 16;

    __shared__ uint32_t Qs[128][20];     // f16x2, [q][d/2]
    __shared__ uint32_t Ks[3][64][20];   // f16x2, triple buffered
    __shared__ uint32_t Vs[3][64][20];

    const uint32_t smQ = (uint32_t)__cvta_generic_to_shared(Qs);
    const uint32_t smK = (uint32_t)__cvta_generic_to_shared(Ks);
    const uint32_t smV = (uint32_t)__cvta_generic_to_shared(Vs);

#pragma unroll
    for (int it = 0; it < 2; it++) {
        int t = tid + it * 256;
        int r = t >> 2, c4 = (t & 3) * 4;
        *(uint4*)&Qs[r][c4] =
            *(const uint4*)&g_qkvh[(size_t)(b * NL + qb + r) * 384 + h * 16 + c4];
    }

    const uint32_t q_ad = smQ + (uint32_t)((qw + (lane & 15)) * 20 + ((lane >> 4) << 2)) * 4;
    const uint32_t k_ad = smK + (uint32_t)(((lane & 7) + ((lane >> 4) << 3)) * 20 +
                                           (((lane >> 3) & 1) << 2)) * 4;
    const uint32_t v_ad = smV + (uint32_t)((lane & 15) * 20 + ((lane >> 4) << 2)) * 4;

    float o[4][4], lacc[4];
#pragma unroll
    for (int nt = 0; nt < 4; nt++)
#pragma unroll
        for (int j = 0; j < 4; j++) o[nt][j] = 0.f;
#pragma unroll
    for (int j = 0; j < 4; j++) lacc[j] = 0.f;
    const uint32_t ones2[2] = {0x3C003C00u, 0x3C003C00u};  // fp16 1.0 x2

    const int fr = tid >> 2, fc4 = (tid & 3) * 4;

#define ATTN_ISSUE(kb, buf)                                                    \
    do {                                                                       \
        size_t base = (size_t)(b * NL + (kb) + fr) * 384 + h * 16 + fc4;       \
        uint32_t off = (uint32_t)((buf) * 1280 + fr * 20 + fc4) * 4;           \
        CP_ASYNC16(smK + off, &g_qkvh[base + 128]);                            \
        CP_ASYNC16(smV + off, &g_qkvh[base + 256]);                            \
    } while (0)

    ATTN_ISSUE(0, 0);
    CP_COMMIT();
    ATTN_ISSUE(64, 1);
    CP_COMMIT();
    __syncthreads();               // Qs visible -> load Q fragments once

    uint32_t qf[2][4];
#pragma unroll
    for (int ks = 0; ks < 2; ks++)
        LDSM4(qf[ks][0], qf[ks][1], qf[ks][2], qf[ks][3], q_ad + ks * 32);

    int buf = 0;
#pragma unroll 1
    for (int it = 0; it < 16; it++) {
        if (it >= 14) CP_WAIT0(); else CP_WAIT1();
        __syncthreads();           // buffer 'it' visible; buffer (it-1)%3 free
        if (it < 14) {
            ATTN_ISSUE((it + 2) * 64, (buf + 2) % 3);
            CP_COMMIT();
        }
        const uint32_t boff = (uint32_t)(buf * 5120);

        // ---- fused S + exp per 16-key tile pair (no cross-tile dependency:
        //      no-max softmax).  Only 8 fp32 scores live at a time. ----
        uint32_t p[8][2];
#pragma unroll
        for (int ntp = 0; ntp < 4; ntp++) {
            float sa[4] = {0.f, 0.f, 0.f, 0.f};
            float sb[4] = {0.f, 0.f, 0.f, 0.f};
#pragma unroll
            for (int ks = 0; ks < 2; ks++) {
                uint32_t b0, b1, b2, b3;
                LDSM4(b0, b1, b2, b3, k_ad + boff + ntp * 1280 + ks * 32);
                uint32_t bfa[2] = {b0, b1};
                uint32_t bfb[2] = {b2, b3};
                MMA_F16(sa, qf[ks], bfa);
                MMA_F16(sb, qf[ks], bfb);
            }
            PACKF16(p[2 * ntp][0], sa[0], sa[1]);       // row g
            PACKF16(p[2 * ntp][1], sa[2], sa[3]);       // row g+8
            PACKF16(p[2 * ntp + 1][0], sb[0], sb[1]);
            PACKF16(p[2 * ntp + 1][1], sb[2], sb[3]);
            EX2H2(p[2 * ntp][0]);
            EX2H2(p[2 * ntp][1]);
            EX2H2(p[2 * ntp + 1][0]);
            EX2H2(p[2 * ntp + 1][1]);
        }

        // ---- O += P V  and  l += P @ ones (row sum via MMA, no shuffles) ----
#pragma unroll
        for (int ks = 0; ks < 4; ks++) {          // 16 keys per step
            uint32_t ap[4] = {p[2 * ks][0], p[2 * ks][1],
                              p[2 * ks + 1][0], p[2 * ks + 1][1]};
            MMA_F16(lacc, ap, ones2);
#pragma unroll
            for (int ntp = 0; ntp < 2; ntp++) {
                uint32_t b0, b1, b2, b3;
                LDSM4T(b0, b1, b2, b3, v_ad + boff + ks * 1280 + ntp * 32);
                uint32_t bfa[2] = {b0, b1};
                uint32_t bfb[2] = {b2, b3};
                MMA_F16(o[2 * ntp], ap, bfa);
                MMA_F16(o[2 * ntp + 1], ap, bfb);
            }
        }
        buf = (buf + 1) % 3;
    }
#undef ATTN_ISSUE

    // lacc[0] = full row-g sum, lacc[2] = full row-(g+8) sum (all lanes agree)
    const float inv0 = 1.f / lacc[0];
    const float inv1 = 1.f / lacc[2];
    const int row = b * NL + qb + qw + g;
#pragma unroll
    for (int nt = 0; nt < 4; nt++) {
        const int colw = h * 16 + nt * 4 + tg;
        uint32_t w0, w1;
        PACKF16(w0, o[nt][0] * inv0, o[nt][1] * inv0);
        PACKF16(w1, o[nt][2] * inv1, o[nt][3] * inv1);
        g_ctxh[(size_t)row * 128 + colw] = w0;
        g_ctxh[(size_t)(row + 8) * 128 + colw] = w1;
    }
}

// ---------------------------------------------------------------------------
// Kernel 4: fused out-projection + residual + LayerNorm -> d_out.
// Block tile 64x256 (full rows), 8 warps (2m x 4n) of 32x64; K = 256.
// Single barrier per K-chunk.
// ---------------------------------------------------------------------------
#define OP_SMEM_WORDS (2 * 2304 + 2 * 9216)

__global__ void __launch_bounds__(256) outproj_ln_kernel(
    const uint32_t* __restrict__ Ctx, const uint32_t* __restrict__ Wh,
    const float* __restrict__ bias, float* __restrict__ outp) {
    extern __shared__ uint32_t sm[];
    __shared__ float s_sum[64][4], s_sq[64][4];
    const int tid = threadIdx.x, wid = tid >> 5, lane = tid & 31;
    const int g = lane >> 2, tg = lane & 3;
    const int m0 = blockIdx.x * 64;
    const int wm = (wid & 1) * 32, wn = (wid >> 1) * 64, nw = wid >> 1;
    const uint32_t smb = (uint32_t)__cvta_generic_to_shared(sm);
    const int a_r = lane & 15, a_c = (lane >> 4) * 4;
    const int b_r = (lane & 7) + ((lane >> 4) << 3), b_c = ((lane >> 3) & 1) * 4;

    float acc[2][8][4];
#pragma unroll
    for (int mt = 0; mt < 2; mt++)
#pragma unroll
        for (int nt = 0; nt < 8; nt++)
#pragma unroll
            for (int j = 0; j < 4; j++) acc[mt][nt][j] = 0.f;

#define OP_ISSUE(cc)                                                           \
    do {                                                                       \
        const int _s = (cc) & 1;                                               \
        _Pragma("unroll")                                                      \
        for (int it = 0; it < 2; it++) {                                       \
            int t = tid + it * 256;                                            \
            int r = t >> 3, c = (t & 7) * 4;                                   \
            CP_ASYNC16(smb + (uint32_t)(_s * 2304 + r * 36 + c) * 4,           \
                       &Ctx[(size_t)(m0 + r) * 128 + (cc) * 32 + c]);          \
        }                                                                      \
        _Pragma("unroll")                                                      \
        for (int it = 0; it < 8; it++) {                                       \
            int t = tid + it * 256;                                            \
            int r = t >> 3, c = (t & 7) * 4;                                   \
            CP_ASYNC16(smb + (uint32_t)(4608 + _s * 9216 + r * 36 + c) * 4,    \
                       &Wh[(size_t)r * 128 + (cc) * 32 + c]);                  \
        }                                                                      \
    } while (0)

    OP_ISSUE(0);
    CP_COMMIT();

#pragma unroll
    for (int cchunk = 0; cchunk < 4; cchunk++) {
        CP_WAIT0();
        __syncthreads();
        if (cchunk < 3) {
            OP_ISSUE(cchunk + 1);
            CP_COMMIT();
        }
        const uint32_t abase = smb + (uint32_t)((cchunk & 1) * 2304) * 4;
        const uint32_t bbase = smb + (uint32_t)(4608 + (cchunk & 1) * 9216) * 4;
#pragma unroll
        for (int ks = 0; ks < 4; ks++) {
            const int k0 = ks * 8;
            uint32_t af[2][4];
#pragma unroll
            for (int mt = 0; mt < 2; mt++)
                LDSM4(af[mt][0], af[mt][1], af[mt][2], af[mt][3],
                      abase + (uint32_t)((wm + mt * 16 + a_r) * 36 + k0 + a_c) * 4);
            uint32_t bf[8][2];
#pragma unroll
            for (int ntp = 0; ntp < 4; ntp++)
                LDSM4(bf[2 * ntp][0], bf[2 * ntp][1], bf[2 * ntp + 1][0], bf[2 * ntp + 1][1],
                      bbase + (uint32_t)((wn + ntp * 16 + b_r) * 36 + k0 + b_c) * 4);
#pragma unroll
            for (int mt = 0; mt < 2; mt++)
#pragma unroll
                for (int nt = 0; nt < 8; nt++)
                    MMA_F16(acc[mt][nt], af[mt], bf[nt]);
        }
    }
#undef OP_ISSUE

#pragma unroll
    for (int mt = 0; mt < 2; mt++)
#pragma unroll
        for (int nt = 0; nt < 8; nt++) {
            const int col = wn + nt * 8 + tg * 2;
            const int rA = m0 + wm + mt * 16 + g;
            const float b0 = bias[col], b1 = bias[col + 1];
            float2 eA = *(const float2*)&g_emb[(size_t)rA * 256 + col];
            float2 eB = *(const float2*)&g_emb[(size_t)(rA + 8) * 256 + col];
            acc[mt][nt][0] += b0 + eA.x;
            acc[mt][nt][1] += b1 + eA.y;
            acc[mt][nt][2] += b0 + eB.x;
            acc[mt][nt][3] += b1 + eB.y;
        }

#pragma unroll
    for (int mt = 0; mt < 2; mt++) {
        float sA = 0.f, qA = 0.f, sB = 0.f, qB = 0.f;
#pragma unroll
        for (int nt = 0; nt < 8; nt++) {
            sA += acc[mt][nt][0] + acc[mt][nt][1];
            qA += acc[mt][nt][0] * acc[mt][nt][0] + acc[mt][nt][1] * acc[mt][nt][1];
            sB += acc[mt][nt][2] + acc[mt][nt][3];
            qB += acc[mt][nt][2] * acc[mt][nt][2] + acc[mt][nt][3] * acc[mt][nt][3];
        }
#pragma unroll
        for (int off = 1; off < 4; off <<= 1) {
            sA += __shfl_xor_sync(0xffffffffu, sA, off);
            qA += __shfl_xor_sync(0xffffffffu, qA, off);
            sB += __shfl_xor_sync(0xffffffffu, sB, off);
            qB += __shfl_xor_sync(0xffffffffu, qB, off);
        }
        if (tg == 0) {
            const int lr = wm + mt * 16 + g;
            s_sum[lr][nw] = sA; s_sq[lr][nw] = qA;
            s_sum[lr + 8][nw] = sB; s_sq[lr + 8][nw] = qB;
        }
    }
    __syncthreads();

#pragma unroll
    for (int mt = 0; mt < 2; mt++) {
        const int lrA = wm + mt * 16 + g, lrB = lrA + 8;
        float tsA = s_sum[lrA][0] + s_sum[lrA][1] + s_sum[lrA][2] + s_sum[lrA][3];
        float tqA = s_sq[lrA][0] + s_sq[lrA][1] + s_sq[lrA][2] + s_sq[lrA][3];
        float tsB = s_sum[lrB][0] + s_sum[lrB][1] + s_sum[lrB][2] + s_sum[lrB][3];
        float tqB = s_sq[lrB][0] + s_sq[lrB][1] + s_sq[lrB][2] + s_sq[lrB][3];
        const float mA = tsA * (1.f / 256.f);
        const float rA = rsqrtf(tqA * (1.f / 256.f) - mA * mA + LN_EPS);
        const float mB = tsB * (1.f / 256.f);
        const float rB = rsqrtf(tqB * (1.f / 256.f) - mB * mB + LN_EPS);
#pragma unroll
        for (int nt = 0; nt < 8; nt++) {
            const int col = wn + nt * 8 + tg * 2;
            float2 vA = make_float2((acc[mt][nt][0] - mA) * rA,
                                    (acc[mt][nt][1] - mA) * rA);
            float2 vB = make_float2((acc[mt][nt][2] - mB) * rB,
                                    (acc[mt][nt][3] - mB) * rB);
            *(float2*)&outp[(size_t)(m0 + lrA) * 256 + col] = vA;
            *(float2*)&outp[(size_t)(m0 + lrB) * 256 + col] = vB;
        }
    }
}

// ---------------------------------------------------------------------------
extern "C" void kernel_launch(void* const* d_in, const int* in_sizes, int n_in,
                              void* d_out, int out_size) {
    const int*   seq   = (const int*)  d_in[0];
    const float* emb_w = (const float*)d_in[1];
    const float* emb_b = (const float*)d_in[2];
    const float* inp_w = (const float*)d_in[3];
    const float* inp_b = (const float*)d_in[4];
    const float* out_w = (const float*)d_in[5];
    const float* out_b = (const float*)d_in[6];
    float* out = (float*)d_out;

    uint32_t *p_embh, *p_qkvh, *p_ctxh, *p_wqkvh, *p_wouth;
    cudaGetSymbolAddress((void**)&p_embh, g_embh);
    cudaGetSymbolAddress((void**)&p_qkvh, g_qkvh);
    cudaGetSymbolAddress((void**)&p_ctxh, g_ctxh);
    cudaGetSymbolAddress((void**)&p_wqkvh, g_wqkvh);
    cudaGetSymbolAddress((void**)&p_wouth, g_wouth);

    const int gemm_smem = GEMM_SMEM_WORDS * 4;   // 73728
    const int op_smem = OP_SMEM_WORDS * 4;       // 92160
    cudaFuncSetAttribute(gemm_qkv_kernel,
                         cudaFuncAttributeMaxDynamicSharedMemorySize, gemm_smem);
    cudaFuncSetAttribute(outproj_ln_kernel,
                         cudaFuncAttributeMaxDynamicSharedMemorySize, op_smem);

    // 0. weight conversion fp32 -> fp16x2 (both matrices, one launch)
    cvtw_kernel<<<(NW1 + NW2 + 255) / 256, 256>>>(inp_w, out_w, p_wqkvh, p_wouth);
    // 1. embedding + LN (fp32 residual + fp16 copy), warp per row
    embed_ln_kernel<<<(NB * NL) / 8, 256>>>(seq, emb_w, emb_b);
    // 2. QKV projection -> packed fp16, Q pre-scaled by SC2F
    gemm_qkv_kernel<<<dim3(NE3 / 128, (NB * NL) / 128), 256, gemm_smem>>>(
        p_embh, p_wqkvh, inp_b, p_qkvh);
    // 3. fused flash attention -> g_ctxh (fp16)
    attn_kernel<<<dim3(NL / 128, NH, NB), 256>>>();
    // 4. out-projection + residual + LN -> d_out
    outproj_ln_kernel<<<(NB * NL) / 64, 256, op_smem>>>(
        p_ctxh, p_wouth, out_b, out);
}

// round 13
// speedup vs baseline: 1.0754x; 1.0227x over previous
#include <cuda_runtime.h>
#include <math.h>
#include <cstdint>

#define NB 16
#define NL 1024
#define NC 4
#define NE 256
#define NH 8
#define NE3 768
#define LN_EPS 1e-5f
// (1/sqrt(32)) * log2(e): exp2-domain softmax scale, folded into Q in the GEMM
#define SC2F 0.25506298365213554f

// Scratch (static device globals — no dynamic allocation allowed)
__device__ __align__(16) float    g_emb[NB * NL * NE];        // fp32 residual
__device__ __align__(16) uint32_t g_embh[NB * NL * NE / 2];   // fp16x2 LN output
__device__ __align__(16) uint32_t g_qkvh[NB * NL * NE3 / 2];  // fp16x2 qkv (q pre-scaled)
__device__ __align__(16) uint32_t g_ctxh[NB * NL * NE / 2];   // fp16x2 context
__device__ __align__(16) uint32_t g_wqkvh[NE3 * NE / 2];      // in_proj_w fp16x2
__device__ __align__(16) uint32_t g_wouth[NE * NE / 2];       // out_w fp16x2

// ---------------------------------------------------------------------------
// PTX helpers (plain ISA only — ptxas targets sm_103 without 'a' features)
// ---------------------------------------------------------------------------
#define MMA_F16(c, a, b)                                                       \
    asm volatile("mma.sync.aligned.m16n8k16.row.col.f32.f16.f16.f32 "          \
        "{%0,%1,%2,%3}, {%4,%5,%6,%7}, {%8,%9}, {%0,%1,%2,%3};"                \
        : "+f"((c)[0]), "+f"((c)[1]), "+f"((c)[2]), "+f"((c)[3])               \
        : "r"((a)[0]), "r"((a)[1]), "r"((a)[2]), "r"((a)[3]),                  \
          "r"((b)[0]), "r"((b)[1]))

#define PACKF16(r, lo, hi)                                                     \
    asm("cvt.rn.f16x2.f32 %0, %1, %2;" : "=r"(r) : "f"(hi), "f"(lo))

// two fp16 exp2 in ONE MUFU op (halves MUFU pressure vs exp2f)
#define EX2H2(r) asm("ex2.approx.f16x2 %0, %0;" : "+r"(r))

#define CP_ASYNC16(dst_u32, src_ptr)                                           \
    asm volatile("cp.async.cg.shared.global [%0], [%1], 16;"                   \
                 :: "r"(dst_u32), "l"(src_ptr))
#define CP_COMMIT() asm volatile("cp.async.commit_group;" ::: "memory")
#define CP_WAIT1()  asm volatile("cp.async.wait_group 1;" ::: "memory")
#define CP_WAIT0()  asm volatile("cp.async.wait_group 0;" ::: "memory")

#define LDSM4(r0, r1, r2, r3, addr)                                            \
    asm volatile("ldmatrix.sync.aligned.m8n8.x4.shared.b16 {%0,%1,%2,%3}, [%4];" \
        : "=r"(r0), "=r"(r1), "=r"(r2), "=r"(r3) : "r"(addr))
#define LDSM4T(r0, r1, r2, r3, addr)                                           \
    asm volatile("ldmatrix.sync.aligned.m8n8.x4.trans.shared.b16 {%0,%1,%2,%3}, [%4];" \
        : "=r"(r0), "=r"(r1), "=r"(r2), "=r"(r3) : "r"(addr))

// ---------------------------------------------------------------------------
// Kernel 0: fp32 -> packed fp16x2 conversion of BOTH weight matrices (1 launch)
// ---------------------------------------------------------------------------
#define NW1 (NE3 * NE / 2)
#define NW2 (NE * NE / 2)
__global__ void cvtw_kernel(const float* __restrict__ src1,
                            const float* __restrict__ src2,
                            uint32_t* __restrict__ dst1,
                            uint32_t* __restrict__ dst2) {
    int i = blockIdx.x * 256 + threadIdx.x;
    if (i < NW1) {
        uint32_t w;
        PACKF16(w, src1[2 * i], src1[2 * i + 1]);
        dst1[i] = w;
    } else {
        int j = i - NW1;
        if (j < NW2) {
            uint32_t w;
            PACKF16(w, src2[2 * j], src2[2 * j + 1]);
            dst2[j] = w;
        }
    }
}

// ---------------------------------------------------------------------------
// Kernel 1: embedding gather + bias + LayerNorm.  Warp per row (8 rows/block):
// warp-shuffle reduction only — no barrier, no smem.
// ---------------------------------------------------------------------------
__global__ void __launch_bounds__(256) embed_ln_kernel(
    const int* __restrict__ seq, const float* __restrict__ emb_w,
    const float* __restrict__ emb_b) {
    const int wid = threadIdx.x >> 5, lane = threadIdx.x & 31;
    const int row = blockIdx.x * 8 + wid;
    const int l = row & (NL - 1);
    const int c = seq[row];

    float v[8];
    float s = 0.f, q = 0.f;
#pragma unroll
    for (int i = 0; i < 8; i++) {
        const int e = lane + 32 * i;
        v[i] = emb_w[(l * NE + e) * NC + c] + emb_b[l * NE + e];
        s += v[i];
        q += v[i] * v[i];
    }
#pragma unroll
    for (int o = 16; o > 0; o >>= 1) {
        s += __shfl_xor_sync(0xffffffffu, s, o);
        q += __shfl_xor_sync(0xffffffffu, q, o);
    }
    const float mean = s * (1.f / NE);
    const float var = q * (1.f / NE) - mean * mean;
    const float r = rsqrtf(var + LN_EPS);
#pragma unroll
    for (int i = 0; i < 8; i++) {
        const int e = lane + 32 * i;
        const float y = (v[i] - mean) * r;
        g_emb[(size_t)row * NE + e] = y;
        const float y1 = __shfl_down_sync(0xffffffffu, y, 1);
        if ((lane & 1) == 0) {
            uint32_t w;
            PACKF16(w, y, y1);
            g_embh[(size_t)row * (NE / 2) + (e >> 1)] = w;
        }
    }
}

// ---------------------------------------------------------------------------
// Kernel 2: QKV fp16 GEMM.  Block tile 128x128, 512 threads = 16 warps
// (4m x 4n) of 32x32 each -> 32 acc regs/thread, ~64 total -> 2 CTAs/SM
// = 1024 resident threads (2x the 256-thread shape).  Same smem layout,
// same single-barrier-per-chunk cp.async pipeline.  Q cols scaled by SC2F.
// ---------------------------------------------------------------------------
#define GEMM_SMEM_WORDS (4 * 4608)     // As[2][128][36] + Bs[2][128][36]

__global__ void __launch_bounds__(512) gemm_qkv_kernel(
    const uint32_t* __restrict__ A, const uint32_t* __restrict__ W,
    const float* __restrict__ bias, uint32_t* __restrict__ C16) {
    extern __shared__ uint32_t sm[];
    const int tid = threadIdx.x, wid = tid >> 5, lane = tid & 31;
    const int g = lane >> 2, tg = lane & 3;
    const int m0 = blockIdx.y * 128, n0 = blockIdx.x * 128;
    const int wm = (wid & 3) * 32, wn = (wid >> 2) * 32;
    const uint32_t smb = (uint32_t)__cvta_generic_to_shared(sm);
    const int a_r = lane & 15, a_c = (lane >> 4) * 4;
    const int b_r = (lane & 7) + ((lane >> 4) << 3), b_c = ((lane >> 3) & 1) * 4;
    const int lr = tid >> 3, lc = (tid & 7) * 4;   // cp.async: rows 0..63 per pass

    float acc[2][4][4];
#pragma unroll
    for (int mt = 0; mt < 2; mt++)
#pragma unroll
        for (int nt = 0; nt < 4; nt++)
#pragma unroll
            for (int j = 0; j < 4; j++) acc[mt][nt][j] = 0.f;

#define QKV_ISSUE(cc)                                                          \
    do {                                                                       \
        const int _s = (cc) & 1;                                               \
        _Pragma("unroll")                                                      \
        for (int it = 0; it < 2; it++) {                                       \
            int row = lr + it * 64;                                            \
            CP_ASYNC16(smb + (uint32_t)(_s * 4608 + row * 36 + lc) * 4,        \
                       &A[(size_t)(m0 + row) * 128 + (cc) * 32 + lc]);         \
        }                                                                      \
        _Pragma("unroll")                                                      \
        for (int it = 0; it < 2; it++) {                                       \
            int row = lr + it * 64;                                            \
            CP_ASYNC16(smb + (uint32_t)(9216 + _s * 4608 + row * 36 + lc) * 4, \
                       &W[(size_t)(n0 + row) * 128 + (cc) * 32 + lc]);         \
        }                                                                      \
    } while (0)

    QKV_ISSUE(0);
    CP_COMMIT();

#pragma unroll
    for (int cchunk = 0; cchunk < 4; cchunk++) {
        CP_WAIT0();
        __syncthreads();            // buffer 'cchunk' visible; stale buffer free
        if (cchunk < 3) {
            QKV_ISSUE(cchunk + 1);
            CP_COMMIT();
        }
        const uint32_t abase = smb + (uint32_t)((cchunk & 1) * 4608) * 4;
        const uint32_t bbase = smb + (uint32_t)(9216 + (cchunk & 1) * 4608) * 4;
#pragma unroll
        for (int ks = 0; ks < 4; ks++) {
            const int k0 = ks * 8;
            uint32_t af[2][4];
#pragma unroll
            for (int mt = 0; mt < 2; mt++)
                LDSM4(af[mt][0], af[mt][1], af[mt][2], af[mt][3],
                      abase + (uint32_t)((wm + mt * 16 + a_r) * 36 + k0 + a_c) * 4);
            uint32_t bf[4][2];
#pragma unroll
            for (int ntp = 0; ntp < 2; ntp++)
                LDSM4(bf[2 * ntp][0], bf[2 * ntp][1], bf[2 * ntp + 1][0], bf[2 * ntp + 1][1],
                      bbase + (uint32_t)((wn + ntp * 16 + b_r) * 36 + k0 + b_c) * 4);
#pragma unroll
            for (int mt = 0; mt < 2; mt++)
#pragma unroll
                for (int nt = 0; nt < 4; nt++)
                    MMA_F16(acc[mt][nt], af[mt], bf[nt]);
        }
    }
#undef QKV_ISSUE

#pragma unroll
    for (int mt = 0; mt < 2; mt++)
#pragma unroll
        for (int nt = 0; nt < 4; nt++) {
            const int row = m0 + wm + mt * 16 + g;
            const int col = n0 + wn + nt * 8 + tg * 2;
            const float scl = (col < 256) ? SC2F : 1.0f;  // Q gets softmax scale
            const float b0 = bias[col], b1 = bias[col + 1];
            const int colw = col >> 1;
            uint32_t w0, w1;
            PACKF16(w0, (acc[mt][nt][0] + b0) * scl, (acc[mt][nt][1] + b1) * scl);
            PACKF16(w1, (acc[mt][nt][2] + b0) * scl, (acc[mt][nt][3] + b1) * scl);
            C16[(size_t)row * 384 + colw] = w0;
            C16[(size_t)(row + 8) * 384 + colw] = w1;
        }
}

// ---------------------------------------------------------------------------
// Kernel 3: fused flash attention.  64-key chunks, triple-buffered static
// smem (40KB), NATURAL register allocation (R11/12 forced cap was a net
// loss: remat cost > occupancy gain).  No-max exp2 softmax consumed per
// 16-key tile pair (8 fp32 scores live); row-sum l via MMA vs all-ones B.
// ---------------------------------------------------------------------------
__global__ void __launch_bounds__(256) attn_kernel() {
    const int qb = blockIdx.x * 128;
    const int h  = blockIdx.y;
    const int b  = blockIdx.z;
    const int tid = threadIdx.x, wid = tid >> 5, lane = tid & 31;
    const int g = lane >> 2, tg = lane & 3;
    const int qw = wid * 16;

    __shared__ uint32_t Qs[128][20];     // f16x2, [q][d/2]
    __shared__ uint32_t Ks[3][64][20];   // f16x2, triple buffered
    __shared__ uint32_t Vs[3][64][20];

    const uint32_t smQ = (uint32_t)__cvta_generic_to_shared(Qs);
    const uint32_t smK = (uint32_t)__cvta_generic_to_shared(Ks);
    const uint32_t smV = (uint32_t)__cvta_generic_to_shared(Vs);

#pragma unroll
    for (int it = 0; it < 2; it++) {
        int t = tid + it * 256;
        int r = t >> 2, c4 = (t & 3) * 4;
        *(uint4*)&Qs[r][c4] =
            *(const uint4*)&g_qkvh[(size_t)(b * NL + qb + r) * 384 + h * 16 + c4];
    }

    const uint32_t q_ad = smQ + (uint32_t)((qw + (lane & 15)) * 20 + ((lane >> 4) << 2)) * 4;
    const uint32_t k_ad = smK + (uint32_t)(((lane & 7) + ((lane >> 4) << 3)) * 20 +
                                           (((lane >> 3) & 1) << 2)) * 4;
    const uint32_t v_ad = smV + (uint32_t)((lane & 15) * 20 + ((lane >> 4) << 2)) * 4;

    float o[4][4], lacc[4];
#pragma unroll
    for (int nt = 0; nt < 4; nt++)
#pragma unroll
        for (int j = 0; j < 4; j++) o[nt][j] = 0.f;
#pragma unroll
    for (int j = 0; j < 4; j++) lacc[j] = 0.f;
    const uint32_t ones2[2] = {0x3C003C00u, 0x3C003C00u};  // fp16 1.0 x2

    const int fr = tid >> 2, fc4 = (tid & 3) * 4;

#define ATTN_ISSUE(kb, buf)                                                    \
    do {                                                                       \
        size_t base = (size_t)(b * NL + (kb) + fr) * 384 + h * 16 + fc4;       \
        uint32_t off = (uint32_t)((buf) * 1280 + fr * 20 + fc4) * 4;           \
        CP_ASYNC16(smK + off, &g_qkvh[base + 128]);                            \
        CP_ASYNC16(smV + off, &g_qkvh[base + 256]);                            \
    } while (0)

    ATTN_ISSUE(0, 0);
    CP_COMMIT();
    ATTN_ISSUE(64, 1);
    CP_COMMIT();
    __syncthreads();               // Qs visible -> load Q fragments once

    uint32_t qf[2][4];
#pragma unroll
    for (int ks = 0; ks < 2; ks++)
        LDSM4(qf[ks][0], qf[ks][1], qf[ks][2], qf[ks][3], q_ad + ks * 32);

    int buf = 0;
#pragma unroll 1
    for (int it = 0; it < 16; it++) {
        if (it >= 14) CP_WAIT0(); else CP_WAIT1();
        __syncthreads();           // buffer 'it' visible; buffer (it-1)%3 free
        if (it < 14) {
            ATTN_ISSUE((it + 2) * 64, (buf + 2) % 3);
            CP_COMMIT();
        }
        const uint32_t boff = (uint32_t)(buf * 5120);

        // ---- fused S + exp per 16-key tile pair (no cross-tile dependency:
        //      no-max softmax).  Only 8 fp32 scores live at a time. ----
        uint32_t p[8][2];
#pragma unroll
        for (int ntp = 0; ntp < 4; ntp++) {
            float sa[4] = {0.f, 0.f, 0.f, 0.f};
            float sb[4] = {0.f, 0.f, 0.f, 0.f};
#pragma unroll
            for (int ks = 0; ks < 2; ks++) {
                uint32_t b0, b1, b2, b3;
                LDSM4(b0, b1, b2, b3, k_ad + boff + ntp * 1280 + ks * 32);
                uint32_t bfa[2] = {b0, b1};
                uint32_t bfb[2] = {b2, b3};
                MMA_F16(sa, qf[ks], bfa);
                MMA_F16(sb, qf[ks], bfb);
            }
            PACKF16(p[2 * ntp][0], sa[0], sa[1]);       // row g
            PACKF16(p[2 * ntp][1], sa[2], sa[3]);       // row g+8
            PACKF16(p[2 * ntp + 1][0], sb[0], sb[1]);
            PACKF16(p[2 * ntp + 1][1], sb[2], sb[3]);
            EX2H2(p[2 * ntp][0]);
            EX2H2(p[2 * ntp][1]);
            EX2H2(p[2 * ntp + 1][0]);
            EX2H2(p[2 * ntp + 1][1]);
        }

        // ---- O += P V  and  l += P @ ones (row sum via MMA, no shuffles) ----
#pragma unroll
        for (int ks = 0; ks < 4; ks++) {          // 16 keys per step
            uint32_t ap[4] = {p[2 * ks][0], p[2 * ks][1],
                              p[2 * ks + 1][0], p[2 * ks + 1][1]};
            MMA_F16(lacc, ap, ones2);
#pragma unroll
            for (int ntp = 0; ntp < 2; ntp++) {
                uint32_t b0, b1, b2, b3;
                LDSM4T(b0, b1, b2, b3, v_ad + boff + ks * 1280 + ntp * 32);
                uint32_t bfa[2] = {b0, b1};
                uint32_t bfb[2] = {b2, b3};
                MMA_F16(o[2 * ntp], ap, bfa);
                MMA_F16(o[2 * ntp + 1], ap, bfb);
            }
        }
        buf = (buf + 1) % 3;
    }
#undef ATTN_ISSUE

    // lacc[0] = full row-g sum, lacc[2] = full row-(g+8) sum (all lanes agree)
    const float inv0 = 1.f / lacc[0];
    const float inv1 = 1.f / lacc[2];
    const int row = b * NL + qb + qw + g;
#pragma unroll
    for (int nt = 0; nt < 4; nt++) {
        const int colw = h * 16 + nt * 4 + tg;
        uint32_t w0, w1;
        PACKF16(w0, o[nt][0] * inv0, o[nt][1] * inv0);
        PACKF16(w1, o[nt][2] * inv1, o[nt][3] * inv1);
        g_ctxh[(size_t)row * 128 + colw] = w0;
        g_ctxh[(size_t)(row + 8) * 128 + colw] = w1;
    }
}

// ---------------------------------------------------------------------------
// Kernel 4: fused out-projection + residual + LayerNorm -> d_out.
// Block tile 64x256 (full rows), 8 warps (2m x 4n) of 32x64; K = 256.
// Single barrier per K-chunk.
// ---------------------------------------------------------------------------
#define OP_SMEM_WORDS (2 * 2304 + 2 * 9216)

__global__ void __launch_bounds__(256) outproj_ln_kernel(
    const uint32_t* __restrict__ Ctx, const uint32_t* __restrict__ Wh,
    const float* __restrict__ bias, float* __restrict__ outp) {
    extern __shared__ uint32_t sm[];
    __shared__ float s_sum[64][4], s_sq[64][4];
    const int tid = threadIdx.x, wid = tid >> 5, lane = tid & 31;
    const int g = lane >> 2, tg = lane & 3;
    const int m0 = blockIdx.x * 64;
    const int wm = (wid & 1) * 32, wn = (wid >> 1) * 64, nw = wid >> 1;
    const uint32_t smb = (uint32_t)__cvta_generic_to_shared(sm);
    const int a_r = lane & 15, a_c = (lane >> 4) * 4;
    const int b_r = (lane & 7) + ((lane >> 4) << 3), b_c = ((lane >> 3) & 1) * 4;

    float acc[2][8][4];
#pragma unroll
    for (int mt = 0; mt < 2; mt++)
#pragma unroll
        for (int nt = 0; nt < 8; nt++)
#pragma unroll
            for (int j = 0; j < 4; j++) acc[mt][nt][j] = 0.f;

#define OP_ISSUE(cc)                                                           \
    do {                                                                       \
        const int _s = (cc) & 1;                                               \
        _Pragma("unroll")                                                      \
        for (int it = 0; it < 2; it++) {                                       \
            int t = tid + it * 256;                                            \
            int r = t >> 3, c = (t & 7) * 4;                                   \
            CP_ASYNC16(smb + (uint32_t)(_s * 2304 + r * 36 + c) * 4,           \
                       &Ctx[(size_t)(m0 + r) * 128 + (cc) * 32 + c]);          \
        }                                                                      \
        _Pragma("unroll")                                                      \
        for (int it = 0; it < 8; it++) {                                       \
            int t = tid + it * 256;                                            \
            int r = t >> 3, c = (t & 7) * 4;                                   \
            CP_ASYNC16(smb + (uint32_t)(4608 + _s * 9216 + r * 36 + c) * 4,    \
                       &Wh[(size_t)r * 128 + (cc) * 32 + c]);                  \
        }                                                                      \
    } while (0)

    OP_ISSUE(0);
    CP_COMMIT();

#pragma unroll
    for (int cchunk = 0; cchunk < 4; cchunk++) {
        CP_WAIT0();
        __syncthreads();
        if (cchunk < 3) {
            OP_ISSUE(cchunk + 1);
            CP_COMMIT();
        }
        const uint32_t abase = smb + (uint32_t)((cchunk & 1) * 2304) * 4;
        const uint32_t bbase = smb + (uint32_t)(4608 + (cchunk & 1) * 9216) * 4;
#pragma unroll
        for (int ks = 0; ks < 4; ks++) {
            const int k0 = ks * 8;
            uint32_t af[2][4];
#pragma unroll
            for (int mt = 0; mt < 2; mt++)
                LDSM4(af[mt][0], af[mt][1], af[mt][2], af[mt][3],
                      abase + (uint32_t)((wm + mt * 16 + a_r) * 36 + k0 + a_c) * 4);
            uint32_t bf[8][2];
#pragma unroll
            for (int ntp = 0; ntp < 4; ntp++)
                LDSM4(bf[2 * ntp][0], bf[2 * ntp][1], bf[2 * ntp + 1][0], bf[2 * ntp + 1][1],
                      bbase + (uint32_t)((wn + ntp * 16 + b_r) * 36 + k0 + b_c) * 4);
#pragma unroll
            for (int mt = 0; mt < 2; mt++)
#pragma unroll
                for (int nt = 0; nt < 8; nt++)
                    MMA_F16(acc[mt][nt], af[mt], bf[nt]);
        }
    }
#undef OP_ISSUE

#pragma unroll
    for (int mt = 0; mt < 2; mt++)
#pragma unroll
        for (int nt = 0; nt < 8; nt++) {
            const int col = wn + nt * 8 + tg * 2;
            const int rA = m0 + wm + mt * 16 + g;
            const float b0 = bias[col], b1 = bias[col + 1];
            float2 eA = *(const float2*)&g_emb[(size_t)rA * 256 + col];
            float2 eB = *(const float2*)&g_emb[(size_t)(rA + 8) * 256 + col];
            acc[mt][nt][0] += b0 + eA.x;
            acc[mt][nt][1] += b1 + eA.y;
            acc[mt][nt][2] += b0 + eB.x;
            acc[mt][nt][3] += b1 + eB.y;
        }

#pragma unroll
    for (int mt = 0; mt < 2; mt++) {
        float sA = 0.f, qA = 0.f, sB = 0.f, qB = 0.f;
#pragma unroll
        for (int nt = 0; nt < 8; nt++) {
            sA += acc[mt][nt][0] + acc[mt][nt][1];
            qA += acc[mt][nt][0] * acc[mt][nt][0] + acc[mt][nt][1] * acc[mt][nt][1];
            sB += acc[mt][nt][2] + acc[mt][nt][3];
            qB += acc[mt][nt][2] * acc[mt][nt][2] + acc[mt][nt][3] * acc[mt][nt][3];
        }
#pragma unroll
        for (int off = 1; off < 4; off <<= 1) {
            sA += __shfl_xor_sync(0xffffffffu, sA, off);
            qA += __shfl_xor_sync(0xffffffffu, qA, off);
            sB += __shfl_xor_sync(0xffffffffu, sB, off);
            qB += __shfl_xor_sync(0xffffffffu, qB, off);
        }
        if (tg == 0) {
            const int lr = wm + mt * 16 + g;
            s_sum[lr][nw] = sA; s_sq[lr][nw] = qA;
            s_sum[lr + 8][nw] = sB; s_sq[lr + 8][nw] = qB;
        }
    }
    __syncthreads();

#pragma unroll
    for (int mt = 0; mt < 2; mt++) {
        const int lrA = wm + mt * 16 + g, lrB = lrA + 8;
        float tsA = s_sum[lrA][0] + s_sum[lrA][1] + s_sum[lrA][2] + s_sum[lrA][3];
        float tqA = s_sq[lrA][0] + s_sq[lrA][1] + s_sq[lrA][2] + s_sq[lrA][3];
        float tsB = s_sum[lrB][0] + s_sum[lrB][1] + s_sum[lrB][2] + s_sum[lrB][3];
        float tqB = s_sq[lrB][0] + s_sq[lrB][1] + s_sq[lrB][2] + s_sq[lrB][3];
        const float mA = tsA * (1.f / 256.f);
        const float rA = rsqrtf(tqA * (1.f / 256.f) - mA * mA + LN_EPS);
        const float mB = tsB * (1.f / 256.f);
        const float rB = rsqrtf(tqB * (1.f / 256.f) - mB * mB + LN_EPS);
#pragma unroll
        for (int nt = 0; nt < 8; nt++) {
            const int col = wn + nt * 8 + tg * 2;
            float2 vA = make_float2((acc[mt][nt][0] - mA) * rA,
                                    (acc[mt][nt][1] - mA) * rA);
            float2 vB = make_float2((acc[mt][nt][2] - mB) * rB,
                                    (acc[mt][nt][3] - mB) * rB);
            *(float2*)&outp[(size_t)(m0 + lrA) * 256 + col] = vA;
            *(float2*)&outp[(size_t)(m0 + lrB) * 256 + col] = vB;
        }
    }
}

// ---------------------------------------------------------------------------
extern "C" void kernel_launch(void* const* d_in, const int* in_sizes, int n_in,
                              void* d_out, int out_size) {
    const int*   seq   = (const int*)  d_in[0];
    const float* emb_w = (const float*)d_in[1];
    const float* emb_b = (const float*)d_in[2];
    const float* inp_w = (const float*)d_in[3];
    const float* inp_b = (const float*)d_in[4];
    const float* out_w = (const float*)d_in[5];
    const float* out_b = (const float*)d_in[6];
    float* out = (float*)d_out;

    uint32_t *p_embh, *p_qkvh, *p_ctxh, *p_wqkvh, *p_wouth;
    cudaGetSymbolAddress((void**)&p_embh, g_embh);
    cudaGetSymbolAddress((void**)&p_qkvh, g_qkvh);
    cudaGetSymbolAddress((void**)&p_ctxh, g_ctxh);
    cudaGetSymbolAddress((void**)&p_wqkvh, g_wqkvh);
    cudaGetSymbolAddress((void**)&p_wouth, g_wouth);

    const int gemm_smem = GEMM_SMEM_WORDS * 4;   // 73728
    const int op_smem = OP_SMEM_WORDS * 4;       // 92160
    cudaFuncSetAttribute(gemm_qkv_kernel,
                         cudaFuncAttributeMaxDynamicSharedMemorySize, gemm_smem);
    cudaFuncSetAttribute(outproj_ln_kernel,
                         cudaFuncAttributeMaxDynamicSharedMemorySize, op_smem);

    // 0. weight conversion fp32 -> fp16x2 (both matrices, one launch)
    cvtw_kernel<<<(NW1 + NW2 + 255) / 256, 256>>>(inp_w, out_w, p_wqkvh, p_wouth);
    // 1. embedding + LN (fp32 residual + fp16 copy), warp per row
    embed_ln_kernel<<<(NB * NL) / 8, 256>>>(seq, emb_w, emb_b);
    // 2. QKV projection -> packed fp16, Q pre-scaled by SC2F (512 threads)
    gemm_qkv_kernel<<<dim3(NE3 / 128, (NB * NL) / 128), 512, gemm_smem>>>(
        p_embh, p_wqkvh, inp_b, p_qkvh);
    // 3. fused flash attention -> g_ctxh (fp16)
    attn_kernel<<<dim3(NL / 128, NH, NB), 256>>>();
    // 4. out-projection + residual + LN -> d_out
    outproj_ln_kernel<<<(NB * NL) / 64, 256, op_smem>>>(
        p_ctxh, p_wouth, out_b, out);
}

// round 14
// speedup vs baseline: 1.0918x; 1.0153x over previous
#include <cuda_runtime.h>
#include <math.h>
#include <cstdint>

#define NB 16
#define NL 1024
#define NC 4
#define NE 256
#define NH 8
#define NE3 768
#define LN_EPS 1e-5f
// (1/sqrt(32)) * log2(e): exp2-domain softmax scale, folded into Q in the GEMM
#define SC2F 0.25506298365213554f

// Scratch (static device globals — no dynamic allocation allowed)
__device__ __align__(16) float    g_emb[NB * NL * NE];        // fp32 residual
__device__ __align__(16) uint32_t g_embh[NB * NL * NE / 2];   // fp16x2 LN output
__device__ __align__(16) uint32_t g_qkvh[NB * NL * NE3 / 2];  // fp16x2 qkv (q pre-scaled)
__device__ __align__(16) uint32_t g_ctxh[NB * NL * NE / 2];   // fp16x2 context
__device__ __align__(16) uint32_t g_wqkvh[NE3 * NE / 2];      // in_proj_w fp16x2
__device__ __align__(16) uint32_t g_wouth[NE * NE / 2];       // out_w fp16x2

// ---------------------------------------------------------------------------
// PTX helpers (plain ISA only — ptxas targets sm_103 without 'a' features)
// ---------------------------------------------------------------------------
#define MMA_F16(c, a, b)                                                       \
    asm volatile("mma.sync.aligned.m16n8k16.row.col.f32.f16.f16.f32 "          \
        "{%0,%1,%2,%3}, {%4,%5,%6,%7}, {%8,%9}, {%0,%1,%2,%3};"                \
        : "+f"((c)[0]), "+f"((c)[1]), "+f"((c)[2]), "+f"((c)[3])               \
        : "r"((a)[0]), "r"((a)[1]), "r"((a)[2]), "r"((a)[3]),                  \
          "r"((b)[0]), "r"((b)[1]))

#define PACKF16(r, lo, hi)                                                     \
    asm("cvt.rn.f16x2.f32 %0, %1, %2;" : "=r"(r) : "f"(hi), "f"(lo))

// two fp16 exp2 in ONE MUFU op (halves MUFU pressure vs exp2f)
#define EX2H2(r) asm("ex2.approx.f16x2 %0, %0;" : "+r"(r))

#define CP_ASYNC16(dst_u32, src_ptr)                                           \
    asm volatile("cp.async.cg.shared.global [%0], [%1], 16;"                   \
                 :: "r"(dst_u32), "l"(src_ptr))
#define CP_COMMIT() asm volatile("cp.async.commit_group;" ::: "memory")
#define CP_WAIT1()  asm volatile("cp.async.wait_group 1;" ::: "memory")
#define CP_WAIT0()  asm volatile("cp.async.wait_group 0;" ::: "memory")

#define LDSM4(r0, r1, r2, r3, addr)                                            \
    asm volatile("ldmatrix.sync.aligned.m8n8.x4.shared.b16 {%0,%1,%2,%3}, [%4];" \
        : "=r"(r0), "=r"(r1), "=r"(r2), "=r"(r3) : "r"(addr))
#define LDSM4T(r0, r1, r2, r3, addr)                                           \
    asm volatile("ldmatrix.sync.aligned.m8n8.x4.trans.shared.b16 {%0,%1,%2,%3}, [%4];" \
        : "=r"(r0), "=r"(r1), "=r"(r2), "=r"(r3) : "r"(addr))

// ---------------------------------------------------------------------------
// Kernel 0: fp32 -> packed fp16x2 conversion of BOTH weight matrices (1 launch)
// ---------------------------------------------------------------------------
#define NW1 (NE3 * NE / 2)
#define NW2 (NE * NE / 2)
__global__ void cvtw_kernel(const float* __restrict__ src1,
                            const float* __restrict__ src2,
                            uint32_t* __restrict__ dst1,
                            uint32_t* __restrict__ dst2) {
    int i = blockIdx.x * 256 + threadIdx.x;
    if (i < NW1) {
        uint32_t w;
        PACKF16(w, src1[2 * i], src1[2 * i + 1]);
        dst1[i] = w;
    } else {
        int j = i - NW1;
        if (j < NW2) {
            uint32_t w;
            PACKF16(w, src2[2 * j], src2[2 * j + 1]);
            dst2[j] = w;
        }
    }
}

// ---------------------------------------------------------------------------
// Kernel 1: embedding gather + bias + LayerNorm.  Warp per row (8 rows/block):
// warp-shuffle reduction only — no barrier, no smem.
// ---------------------------------------------------------------------------
__global__ void __launch_bounds__(256) embed_ln_kernel(
    const int* __restrict__ seq, const float* __restrict__ emb_w,
    const float* __restrict__ emb_b) {
    const int wid = threadIdx.x >> 5, lane = threadIdx.x & 31;
    const int row = blockIdx.x * 8 + wid;
    const int l = row & (NL - 1);
    const int c = seq[row];

    float v[8];
    float s = 0.f, q = 0.f;
#pragma unroll
    for (int i = 0; i < 8; i++) {
        const int e = lane + 32 * i;
        v[i] = emb_w[(l * NE + e) * NC + c] + emb_b[l * NE + e];
        s += v[i];
        q += v[i] * v[i];
    }
#pragma unroll
    for (int o = 16; o > 0; o >>= 1) {
        s += __shfl_xor_sync(0xffffffffu, s, o);
        q += __shfl_xor_sync(0xffffffffu, q, o);
    }
    const float mean = s * (1.f / NE);
    const float var = q * (1.f / NE) - mean * mean;
    const float r = rsqrtf(var + LN_EPS);
#pragma unroll
    for (int i = 0; i < 8; i++) {
        const int e = lane + 32 * i;
        const float y = (v[i] - mean) * r;
        g_emb[(size_t)row * NE + e] = y;
        const float y1 = __shfl_down_sync(0xffffffffu, y, 1);
        if ((lane & 1) == 0) {
            uint32_t w;
            PACKF16(w, y, y1);
            g_embh[(size_t)row * (NE / 2) + (e >> 1)] = w;
        }
    }
}

// ---------------------------------------------------------------------------
// Kernel 2: QKV fp16 GEMM (reverted to R12 shape: 256 threads — the 512-thread
// variant cost ~4us in rest-of-pipeline).  Block tile 128x128, 8 warps
// (4m x 2n) of 32x64.  Single barrier per K-chunk; Q cols scaled by SC2F.
// ---------------------------------------------------------------------------
#define GEMM_SMEM_WORDS (4 * 4608)     // As[2][128][36] + Bs[2][128][36]

__global__ void __launch_bounds__(256) gemm_qkv_kernel(
    const uint32_t* __restrict__ A, const uint32_t* __restrict__ W,
    const float* __restrict__ bias, uint32_t* __restrict__ C16) {
    extern __shared__ uint32_t sm[];
    const int tid = threadIdx.x, wid = tid >> 5, lane = tid & 31;
    const int g = lane >> 2, tg = lane & 3;
    const int m0 = blockIdx.y * 128, n0 = blockIdx.x * 128;
    const int wm = (wid & 3) * 32, wn = (wid >> 2) * 64;
    const uint32_t smb = (uint32_t)__cvta_generic_to_shared(sm);
    const int a_r = lane & 15, a_c = (lane >> 4) * 4;
    const int b_r = (lane & 7) + ((lane >> 4) << 3), b_c = ((lane >> 3) & 1) * 4;

    float acc[2][8][4];
#pragma unroll
    for (int mt = 0; mt < 2; mt++)
#pragma unroll
        for (int nt = 0; nt < 8; nt++)
#pragma unroll
            for (int j = 0; j < 4; j++) acc[mt][nt][j] = 0.f;

#define QKV_ISSUE(cc)                                                          \
    do {                                                                       \
        const int _s = (cc) & 1;                                               \
        _Pragma("unroll")                                                      \
        for (int it = 0; it < 4; it++) {                                       \
            int t = tid + it * 256;                                            \
            int r = t >> 3, c = (t & 7) * 4;                                   \
            CP_ASYNC16(smb + (uint32_t)(_s * 4608 + r * 36 + c) * 4,           \
                       &A[(size_t)(m0 + r) * 128 + (cc) * 32 + c]);            \
        }                                                                      \
        _Pragma("unroll")                                                      \
        for (int it = 0; it < 4; it++) {                                       \
            int t = tid + it * 256;                                            \
            int r = t >> 3, c = (t & 7) * 4;                                   \
            CP_ASYNC16(smb + (uint32_t)(9216 + _s * 4608 + r * 36 + c) * 4,    \
                       &W[(size_t)(n0 + r) * 128 + (cc) * 32 + c]);            \
        }                                                                      \
    } while (0)

    QKV_ISSUE(0);
    CP_COMMIT();

#pragma unroll
    for (int cchunk = 0; cchunk < 4; cchunk++) {
        CP_WAIT0();
        __syncthreads();            // buffer 'cchunk' visible; stale buffer free
        if (cchunk < 3) {
            QKV_ISSUE(cchunk + 1);
            CP_COMMIT();
        }
        const uint32_t abase = smb + (uint32_t)((cchunk & 1) * 4608) * 4;
        const uint32_t bbase = smb + (uint32_t)(9216 + (cchunk & 1) * 4608) * 4;
#pragma unroll
        for (int ks = 0; ks < 4; ks++) {
            const int k0 = ks * 8;
            uint32_t af[2][4];
#pragma unroll
            for (int mt = 0; mt < 2; mt++)
                LDSM4(af[mt][0], af[mt][1], af[mt][2], af[mt][3],
                      abase + (uint32_t)((wm + mt * 16 + a_r) * 36 + k0 + a_c) * 4);
            uint32_t bf[8][2];
#pragma unroll
            for (int ntp = 0; ntp < 4; ntp++)
                LDSM4(bf[2 * ntp][0], bf[2 * ntp][1], bf[2 * ntp + 1][0], bf[2 * ntp + 1][1],
                      bbase + (uint32_t)((wn + ntp * 16 + b_r) * 36 + k0 + b_c) * 4);
#pragma unroll
            for (int mt = 0; mt < 2; mt++)
#pragma unroll
                for (int nt = 0; nt < 8; nt++)
                    MMA_F16(acc[mt][nt], af[mt], bf[nt]);
        }
    }
#undef QKV_ISSUE

#pragma unroll
    for (int mt = 0; mt < 2; mt++)
#pragma unroll
        for (int nt = 0; nt < 8; nt++) {
            const int row = m0 + wm + mt * 16 + g;
            const int col = n0 + wn + nt * 8 + tg * 2;
            const float scl = (col < 256) ? SC2F : 1.0f;  // Q gets softmax scale
            const float b0 = bias[col], b1 = bias[col + 1];
            const int colw = col >> 1;
            uint32_t w0, w1;
            PACKF16(w0, (acc[mt][nt][0] + b0) * scl, (acc[mt][nt][1] + b1) * scl);
            PACKF16(w1, (acc[mt][nt][2] + b0) * scl, (acc[mt][nt][3] + b1) * scl);
            C16[(size_t)row * 384 + colw] = w0;
            C16[(size_t)(row + 8) * 384 + colw] = w1;
        }
}

// ---------------------------------------------------------------------------
// Kernel 3: fused flash attention.  128-thread blocks, 4 warps x 32 q-rows:
// each K/V fragment load feeds TWO A-fragments -> MMA:LDSM 56:16 (was 28:16),
// halving per-FLOP smem traffic (L1 was 64% and co-binding with tensor).
// 64-key chunks, triple-buffered 40KB static smem, no-max exp2 softmax
// (ex2.approx.f16x2), row-sum l via MMA vs all-ones B, Q frags hoisted.
// ---------------------------------------------------------------------------
__global__ void __launch_bounds__(128) attn_kernel() {
    const int qb = blockIdx.x * 128;
    const int h  = blockIdx.y;
    const int b  = blockIdx.z;
    const int tid = threadIdx.x, wid = tid >> 5, lane = tid & 31;
    const int g = lane >> 2, tg = lane & 3;
    const int qw = wid * 32;                    // warp owns 32 q-rows

    __shared__ uint32_t Qs[128][20];     // f16x2, [q][d/2]
    __shared__ uint32_t Ks[3][64][20];   // f16x2, triple buffered
    __shared__ uint32_t Vs[3][64][20];

    const uint32_t smQ = (uint32_t)__cvta_generic_to_shared(Qs);
    const uint32_t smK = (uint32_t)__cvta_generic_to_shared(Ks);
    const uint32_t smV = (uint32_t)__cvta_generic_to_shared(Vs);

#pragma unroll
    for (int it = 0; it < 4; it++) {
        int t = tid + it * 128;
        int r = t >> 2, c4 = (t & 3) * 4;
        *(uint4*)&Qs[r][c4] =
            *(const uint4*)&g_qkvh[(size_t)(b * NL + qb + r) * 384 + h * 16 + c4];
    }

    const uint32_t q_ad = smQ + (uint32_t)((qw + (lane & 15)) * 20 + ((lane >> 4) << 2)) * 4;
    const uint32_t k_ad = smK + (uint32_t)(((lane & 7) + ((lane >> 4) << 3)) * 20 +
                                           (((lane >> 3) & 1) << 2)) * 4;
    const uint32_t v_ad = smV + (uint32_t)((lane & 15) * 20 + ((lane >> 4) << 2)) * 4;

    float o[2][4][4], lacc[2][4];
#pragma unroll
    for (int mt = 0; mt < 2; mt++) {
#pragma unroll
        for (int nt = 0; nt < 4; nt++)
#pragma unroll
            for (int j = 0; j < 4; j++) o[mt][nt][j] = 0.f;
#pragma unroll
        for (int j = 0; j < 4; j++) lacc[mt][j] = 0.f;
    }
    const uint32_t ones2[2] = {0x3C003C00u, 0x3C003C00u};  // fp16 1.0 x2

    // K/V chunk loader: 128 threads, 2 threads/row, 2 uint4 each per tensor
    const int fr = tid >> 1, fc = (tid & 1) * 8;

#define ATTN_ISSUE(kb, buf)                                                    \
    do {                                                                       \
        size_t base = (size_t)(b * NL + (kb) + fr) * 384 + h * 16 + fc;        \
        uint32_t off = (uint32_t)((buf) * 1280 + fr * 20 + fc) * 4;            \
        CP_ASYNC16(smK + off, &g_qkvh[base + 128]);                            \
        CP_ASYNC16(smK + off + 16, &g_qkvh[base + 132]);                       \
        CP_ASYNC16(smV + off, &g_qkvh[base + 256]);                            \
        CP_ASYNC16(smV + off + 16, &g_qkvh[base + 260]);                       \
    } while (0)

    ATTN_ISSUE(0, 0);
    CP_COMMIT();
    ATTN_ISSUE(64, 1);
    CP_COMMIT();
    __syncthreads();               // Qs visible -> load Q fragments once

    uint32_t qf[2][2][4];          // [m-frag][k-step]
#pragma unroll
    for (int mt = 0; mt < 2; mt++)
#pragma unroll
        for (int ks = 0; ks < 2; ks++)
            LDSM4(qf[mt][ks][0], qf[mt][ks][1], qf[mt][ks][2], qf[mt][ks][3],
                  q_ad + (uint32_t)(mt * 16 * 20 * 4) + ks * 32);

    int buf = 0;
#pragma unroll 1
    for (int it = 0; it < 16; it++) {
        if (it >= 14) CP_WAIT0(); else CP_WAIT1();
        __syncthreads();           // buffer 'it' visible; buffer (it-1)%3 free
        if (it < 14) {
            ATTN_ISSUE((it + 2) * 64, (buf + 2) % 3);
            CP_COMMIT();
        }
        const uint32_t boff = (uint32_t)(buf * 5120);

        // ---- fused S + exp per 16-key tile pair; each K frag feeds 2 m-frags
        uint32_t p[2][8][2];
#pragma unroll
        for (int ntp = 0; ntp < 4; ntp++) {
            float sa[2][4] = {{0.f, 0.f, 0.f, 0.f}, {0.f, 0.f, 0.f, 0.f}};
            float sb[2][4] = {{0.f, 0.f, 0.f, 0.f}, {0.f, 0.f, 0.f, 0.f}};
#pragma unroll
            for (int ks = 0; ks < 2; ks++) {
                uint32_t b0, b1, b2, b3;
                LDSM4(b0, b1, b2, b3, k_ad + boff + ntp * 1280 + ks * 32);
                uint32_t bfa[2] = {b0, b1};
                uint32_t bfb[2] = {b2, b3};
#pragma unroll
                for (int mt = 0; mt < 2; mt++) {
                    MMA_F16(sa[mt], qf[mt][ks], bfa);
                    MMA_F16(sb[mt], qf[mt][ks], bfb);
                }
            }
#pragma unroll
            for (int mt = 0; mt < 2; mt++) {
                PACKF16(p[mt][2 * ntp][0], sa[mt][0], sa[mt][1]);
                PACKF16(p[mt][2 * ntp][1], sa[mt][2], sa[mt][3]);
                PACKF16(p[mt][2 * ntp + 1][0], sb[mt][0], sb[mt][1]);
                PACKF16(p[mt][2 * ntp + 1][1], sb[mt][2], sb[mt][3]);
                EX2H2(p[mt][2 * ntp][0]);
                EX2H2(p[mt][2 * ntp][1]);
                EX2H2(p[mt][2 * ntp + 1][0]);
                EX2H2(p[mt][2 * ntp + 1][1]);
            }
        }

        // ---- O += P V ; l += P @ ones.  V frags shared across both m-frags.
#pragma unroll
        for (int ks = 0; ks < 4; ks++) {          // 16 keys per step
            uint32_t ap0[4] = {p[0][2 * ks][0], p[0][2 * ks][1],
                               p[0][2 * ks + 1][0], p[0][2 * ks + 1][1]};
            uint32_t ap1[4] = {p[1][2 * ks][0], p[1][2 * ks][1],
                               p[1][2 * ks + 1][0], p[1][2 * ks + 1][1]};
            MMA_F16(lacc[0], ap0, ones2);
            MMA_F16(lacc[1], ap1, ones2);
#pragma unroll
            for (int ntp = 0; ntp < 2; ntp++) {
                uint32_t b0, b1, b2, b3;
                LDSM4T(b0, b1, b2, b3, v_ad + boff + ks * 1280 + ntp * 32);
                uint32_t bfa[2] = {b0, b1};
                uint32_t bfb[2] = {b2, b3};
                MMA_F16(o[0][2 * ntp], ap0, bfa);
                MMA_F16(o[0][2 * ntp + 1], ap0, bfb);
                MMA_F16(o[1][2 * ntp], ap1, bfa);
                MMA_F16(o[1][2 * ntp + 1], ap1, bfb);
            }
        }
        buf = (buf + 1) % 3;
    }
#undef ATTN_ISSUE

#pragma unroll
    for (int mt = 0; mt < 2; mt++) {
        const float inv0 = 1.f / lacc[mt][0];
        const float inv1 = 1.f / lacc[mt][2];
        const int row = b * NL + qb + qw + mt * 16 + g;
#pragma unroll
        for (int nt = 0; nt < 4; nt++) {
            const int colw = h * 16 + nt * 4 + tg;
            uint32_t w0, w1;
            PACKF16(w0, o[mt][nt][0] * inv0, o[mt][nt][1] * inv0);
            PACKF16(w1, o[mt][nt][2] * inv1, o[mt][nt][3] * inv1);
            g_ctxh[(size_t)row * 128 + colw] = w0;
            g_ctxh[(size_t)(row + 8) * 128 + colw] = w1;
        }
    }
}

// ---------------------------------------------------------------------------
// Kernel 4: fused out-projection + residual + LayerNorm -> d_out.
// Block tile 64x256 (full rows), 8 warps (2m x 4n) of 32x64; K = 256.
// Single barrier per K-chunk.
// ---------------------------------------------------------------------------
#define OP_SMEM_WORDS (2 * 2304 + 2 * 9216)

__global__ void __launch_bounds__(256) outproj_ln_kernel(
    const uint32_t* __restrict__ Ctx, const uint32_t* __restrict__ Wh,
    const float* __restrict__ bias, float* __restrict__ outp) {
    extern __shared__ uint32_t sm[];
    __shared__ float s_sum[64][4], s_sq[64][4];
    const int tid = threadIdx.x, wid = tid >> 5, lane = tid & 31;
    const int g = lane >> 2, tg = lane & 3;
    const int m0 = blockIdx.x * 64;
    const int wm = (wid & 1) * 32, wn = (wid >> 1) * 64, nw = wid >> 1;
    const uint32_t smb = (uint32_t)__cvta_generic_to_shared(sm);
    const int a_r = lane & 15, a_c = (lane >> 4) * 4;
    const int b_r = (lane & 7) + ((lane >> 4) << 3), b_c = ((lane >> 3) & 1) * 4;

    float acc[2][8][4];
#pragma unroll
    for (int mt = 0; mt < 2; mt++)
#pragma unroll
        for (int nt = 0; nt < 8; nt++)
#pragma unroll
            for (int j = 0; j < 4; j++) acc[mt][nt][j] = 0.f;

#define OP_ISSUE(cc)                                                           \
    do {                                                                       \
        const int _s = (cc) & 1;                                               \
        _Pragma("unroll")                                                      \
        for (int it = 0; it < 2; it++) {                                       \
            int t = tid + it * 256;                                            \
            int r = t >> 3, c = (t & 7) * 4;                                   \
            CP_ASYNC16(smb + (uint32_t)(_s * 2304 + r * 36 + c) * 4,           \
                       &Ctx[(size_t)(m0 + r) * 128 + (cc) * 32 + c]);          \
        }                                                                      \
        _Pragma("unroll")                                                      \
        for (int it = 0; it < 8; it++) {                                       \
            int t = tid + it * 256;                                            \
            int r = t >> 3, c = (t & 7) * 4;                                   \
            CP_ASYNC16(smb + (uint32_t)(4608 + _s * 9216 + r * 36 + c) * 4,    \
                       &Wh[(size_t)r * 128 + (cc) * 32 + c]);                  \
        }                                                                      \
    } while (0)

    OP_ISSUE(0);
    CP_COMMIT();

#pragma unroll
    for (int cchunk = 0; cchunk < 4; cchunk++) {
        CP_WAIT0();
        __syncthreads();
        if (cchunk < 3) {
            OP_ISSUE(cchunk + 1);
            CP_COMMIT();
        }
        const uint32_t abase = smb + (uint32_t)((cchunk & 1) * 2304) * 4;
        const uint32_t bbase = smb + (uint32_t)(4608 + (cchunk & 1) * 9216) * 4;
#pragma unroll
        for (int ks = 0; ks < 4; ks++) {
            const int k0 = ks * 8;
            uint32_t af[2][4];
#pragma unroll
            for (int mt = 0; mt < 2; mt++)
                LDSM4(af[mt][0], af[mt][1], af[mt][2], af[mt][3],
                      abase + (uint32_t)((wm + mt * 16 + a_r) * 36 + k0 + a_c) * 4);
            uint32_t bf[8][2];
#pragma unroll
            for (int ntp = 0; ntp < 4; ntp++)
                LDSM4(bf[2 * ntp][0], bf[2 * ntp][1], bf[2 * ntp + 1][0], bf[2 * ntp + 1][1],
                      bbase + (uint32_t)((wn + ntp * 16 + b_r) * 36 + k0 + b_c) * 4);
#pragma unroll
            for (int mt = 0; mt < 2; mt++)
#pragma unroll
                for (int nt = 0; nt < 8; nt++)
                    MMA_F16(acc[mt][nt], af[mt], bf[nt]);
        }
    }
#undef OP_ISSUE

#pragma unroll
    for (int mt = 0; mt < 2; mt++)
#pragma unroll
        for (int nt = 0; nt < 8; nt++) {
            const int col = wn + nt * 8 + tg * 2;
            const int rA = m0 + wm + mt * 16 + g;
            const float b0 = bias[col], b1 = bias[col + 1];
            float2 eA = *(const float2*)&g_emb[(size_t)rA * 256 + col];
            float2 eB = *(const float2*)&g_emb[(size_t)(rA + 8) * 256 + col];
            acc[mt][nt][0] += b0 + eA.x;
            acc[mt][nt][1] += b1 + eA.y;
            acc[mt][nt][2] += b0 + eB.x;
            acc[mt][nt][3] += b1 + eB.y;
        }

#pragma unroll
    for (int mt = 0; mt < 2; mt++) {
        float sA = 0.f, qA = 0.f, sB = 0.f, qB = 0.f;
#pragma unroll
        for (int nt = 0; nt < 8; nt++) {
            sA += acc[mt][nt][0] + acc[mt][nt][1];
            qA += acc[mt][nt][0] * acc[mt][nt][0] + acc[mt][nt][1] * acc[mt][nt][1];
            sB += acc[mt][nt][2] + acc[mt][nt][3];
            qB += acc[mt][nt][2] * acc[mt][nt][2] + acc[mt][nt][3] * acc[mt][nt][3];
        }
#pragma unroll
        for (int off = 1; off < 4; off <<= 1) {
            sA += __shfl_xor_sync(0xffffffffu, sA, off);
            qA += __shfl_xor_sync(0xffffffffu, qA, off);
            sB += __shfl_xor_sync(0xffffffffu, sB, off);
            qB += __shfl_xor_sync(0xffffffffu, qB, off);
        }
        if (tg == 0) {
            const int lr = wm + mt * 16 + g;
            s_sum[lr][nw] = sA; s_sq[lr][nw] = qA;
            s_sum[lr + 8][nw] = sB; s_sq[lr + 8][nw] = qB;
        }
    }
    __syncthreads();

#pragma unroll
    for (int mt = 0; mt < 2; mt++) {
        const int lrA = wm + mt * 16 + g, lrB = lrA + 8;
        float tsA = s_sum[lrA][0] + s_sum[lrA][1] + s_sum[lrA][2] + s_sum[lrA][3];
        float tqA = s_sq[lrA][0] + s_sq[lrA][1] + s_sq[lrA][2] + s_sq[lrA][3];
        float tsB = s_sum[lrB][0] + s_sum[lrB][1] + s_sum[lrB][2] + s_sum[lrB][3];
        float tqB = s_sq[lrB][0] + s_sq[lrB][1] + s_sq[lrB][2] + s_sq[lrB][3];
        const float mA = tsA * (1.f / 256.f);
        const float rA = rsqrtf(tqA * (1.f / 256.f) - mA * mA + LN_EPS);
        const float mB = tsB * (1.f / 256.f);
        const float rB = rsqrtf(tqB * (1.f / 256.f) - mB * mB + LN_EPS);
#pragma unroll
        for (int nt = 0; nt < 8; nt++) {
            const int col = wn + nt * 8 + tg * 2;
            float2 vA = make_float2((acc[mt][nt][0] - mA) * rA,
                                    (acc[mt][nt][1] - mA) * rA);
            float2 vB = make_float2((acc[mt][nt][2] - mB) * rB,
                                    (acc[mt][nt][3] - mB) * rB);
            *(float2*)&outp[(size_t)(m0 + lrA) * 256 + col] = vA;
            *(float2*)&outp[(size_t)(m0 + lrB) * 256 + col] = vB;
        }
    }
}

// ---------------------------------------------------------------------------
extern "C" void kernel_launch(void* const* d_in, const int* in_sizes, int n_in,
                              void* d_out, int out_size) {
    const int*   seq   = (const int*)  d_in[0];
    const float* emb_w = (const float*)d_in[1];
    const float* emb_b = (const float*)d_in[2];
    const float* inp_w = (const float*)d_in[3];
    const float* inp_b = (const float*)d_in[4];
    const float* out_w = (const float*)d_in[5];
    const float* out_b = (const float*)d_in[6];
    float* out = (float*)d_out;

    uint32_t *p_embh, *p_qkvh, *p_ctxh, *p_wqkvh, *p_wouth;
    cudaGetSymbolAddress((void**)&p_embh, g_embh);
    cudaGetSymbolAddress((void**)&p_qkvh, g_qkvh);
    cudaGetSymbolAddress((void**)&p_ctxh, g_ctxh);
    cudaGetSymbolAddress((void**)&p_wqkvh, g_wqkvh);
    cudaGetSymbolAddress((void**)&p_wouth, g_wouth);

    const int gemm_smem = GEMM_SMEM_WORDS * 4;   // 73728
    const int op_smem = OP_SMEM_WORDS * 4;       // 92160
    cudaFuncSetAttribute(gemm_qkv_kernel,
                         cudaFuncAttributeMaxDynamicSharedMemorySize, gemm_smem);
    cudaFuncSetAttribute(outproj_ln_kernel,
                         cudaFuncAttributeMaxDynamicSharedMemorySize, op_smem);

    // 0. weight conversion fp32 -> fp16x2 (both matrices, one launch)
    cvtw_kernel<<<(NW1 + NW2 + 255) / 256, 256>>>(inp_w, out_w, p_wqkvh, p_wouth);
    // 1. embedding + LN (fp32 residual + fp16 copy), warp per row
    embed_ln_kernel<<<(NB * NL) / 8, 256>>>(seq, emb_w, emb_b);
    // 2. QKV projection -> packed fp16, Q pre-scaled by SC2F
    gemm_qkv_kernel<<<dim3(NE3 / 128, (NB * NL) / 128), 256, gemm_smem>>>(
        p_embh, p_wqkvh, inp_b, p_qkvh);
    // 3. fused flash attention -> g_ctxh (fp16), 128 threads / 4 warps
    attn_kernel<<<dim3(NL / 128, NH, NB), 128>>>();
    // 4. out-projection + residual + LN -> d_out
    outproj_ln_kernel<<<(NB * NL) / 64, 256, op_smem>>>(
        p_ctxh, p_wouth, out_b, out);
}

// round 15
// speedup vs baseline: 1.0964x; 1.0042x over previous
#include <cuda_runtime.h>
#include <math.h>
#include <cstdint>

#define NB 16
#define NL 1024
#define NC 4
#define NE 256
#define NH 8
#define NE3 768
#define LN_EPS 1e-5f
// (1/sqrt(32)) * log2(e): exp2-domain softmax scale, folded into Q in the GEMM
#define SC2F 0.25506298365213554f

// Scratch (static device globals — no dynamic allocation allowed)
__device__ __align__(16) float    g_emb[NB * NL * NE];        // fp32 residual
__device__ __align__(16) uint32_t g_embh[NB * NL * NE / 2];   // fp16x2 LN output
__device__ __align__(16) uint32_t g_qkvh[NB * NL * NE3 / 2];  // fp16x2 qkv (q pre-scaled)
__device__ __align__(16) uint32_t g_ctxh[NB * NL * NE / 2];   // fp16x2 context
__device__ __align__(16) uint32_t g_wqkvh[NE3 * NE / 2];      // in_proj_w fp16x2
__device__ __align__(16) uint32_t g_wouth[NE * NE / 2];       // out_w fp16x2

// ---------------------------------------------------------------------------
// PTX helpers (plain ISA only — ptxas targets sm_103 without 'a' features)
// ---------------------------------------------------------------------------
#define MMA_F16(c, a, b)                                                       \
    asm volatile("mma.sync.aligned.m16n8k16.row.col.f32.f16.f16.f32 "          \
        "{%0,%1,%2,%3}, {%4,%5,%6,%7}, {%8,%9}, {%0,%1,%2,%3};"                \
        : "+f"((c)[0]), "+f"((c)[1]), "+f"((c)[2]), "+f"((c)[3])               \
        : "r"((a)[0]), "r"((a)[1]), "r"((a)[2]), "r"((a)[3]),                  \
          "r"((b)[0]), "r"((b)[1]))

// fp16-accumulate variant: D/C are 2 regs of packed f16x2; D-fragment layout
// reg0 = (row g, cols 2tg,2tg+1), reg1 = (row g+8, same) — i.e. exactly the
// packed-p layout the PV stage consumes.  2x rate vs f32-accum on HMMA.
#define MMA_F16ACC(c, a, b)                                                    \
    asm volatile("mma.sync.aligned.m16n8k16.row.col.f16.f16.f16.f16 "          \
        "{%0,%1}, {%2,%3,%4,%5}, {%6,%7}, {%0,%1};"                            \
        : "+r"((c)[0]), "+r"((c)[1])                                           \
        : "r"((a)[0]), "r"((a)[1]), "r"((a)[2]), "r"((a)[3]),                  \
          "r"((b)[0]), "r"((b)[1]))

#define PACKF16(r, lo, hi)                                                     \
    asm("cvt.rn.f16x2.f32 %0, %1, %2;" : "=r"(r) : "f"(hi), "f"(lo))

// two fp16 exp2 in ONE MUFU op (halves MUFU pressure vs exp2f)
#define EX2H2(r) asm("ex2.approx.f16x2 %0, %0;" : "+r"(r))

#define CP_ASYNC16(dst_u32, src_ptr)                                           \
    asm volatile("cp.async.cg.shared.global [%0], [%1], 16;"                   \
                 :: "r"(dst_u32), "l"(src_ptr))
#define CP_COMMIT() asm volatile("cp.async.commit_group;" ::: "memory")
#define CP_WAIT1()  asm volatile("cp.async.wait_group 1;" ::: "memory")
#define CP_WAIT0()  asm volatile("cp.async.wait_group 0;" ::: "memory")

#define LDSM4(r0, r1, r2, r3, addr)                                            \
    asm volatile("ldmatrix.sync.aligned.m8n8.x4.shared.b16 {%0,%1,%2,%3}, [%4];" \
        : "=r"(r0), "=r"(r1), "=r"(r2), "=r"(r3) : "r"(addr))
#define LDSM4T(r0, r1, r2, r3, addr)                                           \
    asm volatile("ldmatrix.sync.aligned.m8n8.x4.trans.shared.b16 {%0,%1,%2,%3}, [%4];" \
        : "=r"(r0), "=r"(r1), "=r"(r2), "=r"(r3) : "r"(addr))

// ---------------------------------------------------------------------------
// Kernel 0: fp32 -> packed fp16x2 conversion of BOTH weight matrices (1 launch)
// ---------------------------------------------------------------------------
#define NW1 (NE3 * NE / 2)
#define NW2 (NE * NE / 2)
__global__ void cvtw_kernel(const float* __restrict__ src1,
                            const float* __restrict__ src2,
                            uint32_t* __restrict__ dst1,
                            uint32_t* __restrict__ dst2) {
    int i = blockIdx.x * 256 + threadIdx.x;
    if (i < NW1) {
        uint32_t w;
        PACKF16(w, src1[2 * i], src1[2 * i + 1]);
        dst1[i] = w;
    } else {
        int j = i - NW1;
        if (j < NW2) {
            uint32_t w;
            PACKF16(w, src2[2 * j], src2[2 * j + 1]);
            dst2[j] = w;
        }
    }
}

// ---------------------------------------------------------------------------
// Kernel 1: embedding gather + bias + LayerNorm.  Warp per row (8 rows/block):
// warp-shuffle reduction only — no barrier, no smem.
// ---------------------------------------------------------------------------
__global__ void __launch_bounds__(256) embed_ln_kernel(
    const int* __restrict__ seq, const float* __restrict__ emb_w,
    const float* __restrict__ emb_b) {
    const int wid = threadIdx.x >> 5, lane = threadIdx.x & 31;
    const int row = blockIdx.x * 8 + wid;
    const int l = row & (NL - 1);
    const int c = seq[row];

    float v[8];
    float s = 0.f, q = 0.f;
#pragma unroll
    for (int i = 0; i < 8; i++) {
        const int e = lane + 32 * i;
        v[i] = emb_w[(l * NE + e) * NC + c] + emb_b[l * NE + e];
        s += v[i];
        q += v[i] * v[i];
    }
#pragma unroll
    for (int o = 16; o > 0; o >>= 1) {
        s += __shfl_xor_sync(0xffffffffu, s, o);
        q += __shfl_xor_sync(0xffffffffu, q, o);
    }
    const float mean = s * (1.f / NE);
    const float var = q * (1.f / NE) - mean * mean;
    const float r = rsqrtf(var + LN_EPS);
#pragma unroll
    for (int i = 0; i < 8; i++) {
        const int e = lane + 32 * i;
        const float y = (v[i] - mean) * r;
        g_emb[(size_t)row * NE + e] = y;
        const float y1 = __shfl_down_sync(0xffffffffu, y, 1);
        if ((lane & 1) == 0) {
            uint32_t w;
            PACKF16(w, y, y1);
            g_embh[(size_t)row * (NE / 2) + (e >> 1)] = w;
        }
    }
}

// ---------------------------------------------------------------------------
// Kernel 2: QKV fp16 GEMM (256 threads).  Block tile 128x128, 8 warps
// (4m x 2n) of 32x64.  Single barrier per K-chunk; Q cols scaled by SC2F.
// ---------------------------------------------------------------------------
#define GEMM_SMEM_WORDS (4 * 4608)     // As[2][128][36] + Bs[2][128][36]

__global__ void __launch_bounds__(256) gemm_qkv_kernel(
    const uint32_t* __restrict__ A, const uint32_t* __restrict__ W,
    const float* __restrict__ bias, uint32_t* __restrict__ C16) {
    extern __shared__ uint32_t sm[];
    const int tid = threadIdx.x, wid = tid >> 5, lane = tid & 31;
    const int g = lane >> 2, tg = lane & 3;
    const int m0 = blockIdx.y * 128, n0 = blockIdx.x * 128;
    const int wm = (wid & 3) * 32, wn = (wid >> 2) * 64;
    const uint32_t smb = (uint32_t)__cvta_generic_to_shared(sm);
    const int a_r = lane & 15, a_c = (lane >> 4) * 4;
    const int b_r = (lane & 7) + ((lane >> 4) << 3), b_c = ((lane >> 3) & 1) * 4;

    float acc[2][8][4];
#pragma unroll
    for (int mt = 0; mt < 2; mt++)
#pragma unroll
        for (int nt = 0; nt < 8; nt++)
#pragma unroll
            for (int j = 0; j < 4; j++) acc[mt][nt][j] = 0.f;

#define QKV_ISSUE(cc)                                                          \
    do {                                                                       \
        const int _s = (cc) & 1;                                               \
        _Pragma("unroll")                                                      \
        for (int it = 0; it < 4; it++) {                                       \
            int t = tid + it * 256;                                            \
            int r = t >> 3, c = (t & 7) * 4;                                   \
            CP_ASYNC16(smb + (uint32_t)(_s * 4608 + r * 36 + c) * 4,           \
                       &A[(size_t)(m0 + r) * 128 + (cc) * 32 + c]);            \
        }                                                                      \
        _Pragma("unroll")                                                      \
        for (int it = 0; it < 4; it++) {                                       \
            int t = tid + it * 256;                                            \
            int r = t >> 3, c = (t & 7) * 4;                                   \
            CP_ASYNC16(smb + (uint32_t)(9216 + _s * 4608 + r * 36 + c) * 4,    \
                       &W[(size_t)(n0 + r) * 128 + (cc) * 32 + c]);            \
        }                                                                      \
    } while (0)

    QKV_ISSUE(0);
    CP_COMMIT();

#pragma unroll
    for (int cchunk = 0; cchunk < 4; cchunk++) {
        CP_WAIT0();
        __syncthreads();            // buffer 'cchunk' visible; stale buffer free
        if (cchunk < 3) {
            QKV_ISSUE(cchunk + 1);
            CP_COMMIT();
        }
        const uint32_t abase = smb + (uint32_t)((cchunk & 1) * 4608) * 4;
        const uint32_t bbase = smb + (uint32_t)(9216 + (cchunk & 1) * 4608) * 4;
#pragma unroll
        for (int ks = 0; ks < 4; ks++) {
            const int k0 = ks * 8;
            uint32_t af[2][4];
#pragma unroll
            for (int mt = 0; mt < 2; mt++)
                LDSM4(af[mt][0], af[mt][1], af[mt][2], af[mt][3],
                      abase + (uint32_t)((wm + mt * 16 + a_r) * 36 + k0 + a_c) * 4);
            uint32_t bf[8][2];
#pragma unroll
            for (int ntp = 0; ntp < 4; ntp++)
                LDSM4(bf[2 * ntp][0], bf[2 * ntp][1], bf[2 * ntp + 1][0], bf[2 * ntp + 1][1],
                      bbase + (uint32_t)((wn + ntp * 16 + b_r) * 36 + k0 + b_c) * 4);
#pragma unroll
            for (int mt = 0; mt < 2; mt++)
#pragma unroll
                for (int nt = 0; nt < 8; nt++)
                    MMA_F16(acc[mt][nt], af[mt], bf[nt]);
        }
    }
#undef QKV_ISSUE

#pragma unroll
    for (int mt = 0; mt < 2; mt++)
#pragma unroll
        for (int nt = 0; nt < 8; nt++) {
            const int row = m0 + wm + mt * 16 + g;
            const int col = n0 + wn + nt * 8 + tg * 2;
            const float scl = (col < 256) ? SC2F : 1.0f;  // Q gets softmax scale
            const float b0 = bias[col], b1 = bias[col + 1];
            const int colw = col >> 1;
            uint32_t w0, w1;
            PACKF16(w0, (acc[mt][nt][0] + b0) * scl, (acc[mt][nt][1] + b1) * scl);
            PACKF16(w1, (acc[mt][nt][2] + b0) * scl, (acc[mt][nt][3] + b1) * scl);
            C16[(size_t)row * 384 + colw] = w0;
            C16[(size_t)(row + 8) * 384 + colw] = w1;
        }
}

// ---------------------------------------------------------------------------
// Kernel 3: fused flash attention.  128-thread blocks, 4 warps x 32 q-rows.
// S computed with fp16-ACCUMULATE MMA (2x HMMA rate; D-frag is already the
// packed-p fp16x2 layout -> zero cvt ops; EX2H2 applied in place).
// PV + row-sum l stay fp32-accum.  64-key chunks, triple-buffered 40KB smem,
// no-max exp2 softmax, Q frags hoisted.
// ---------------------------------------------------------------------------
__global__ void __launch_bounds__(128) attn_kernel() {
    const int qb = blockIdx.x * 128;
    const int h  = blockIdx.y;
    const int b  = blockIdx.z;
    const int tid = threadIdx.x, wid = tid >> 5, lane = tid & 31;
    const int g = lane >> 2, tg = lane & 3;
    const int qw = wid * 32;                    // warp owns 32 q-rows

    __shared__ uint32_t Qs[128][20];     // f16x2, [q][d/2]
    __shared__ uint32_t Ks[3][64][20];   // f16x2, triple buffered
    __shared__ uint32_t Vs[3][64][20];

    const uint32_t smQ = (uint32_t)__cvta_generic_to_shared(Qs);
    const uint32_t smK = (uint32_t)__cvta_generic_to_shared(Ks);
    const uint32_t smV = (uint32_t)__cvta_generic_to_shared(Vs);

#pragma unroll
    for (int it = 0; it < 4; it++) {
        int t = tid + it * 128;
        int r = t >> 2, c4 = (t & 3) * 4;
        *(uint4*)&Qs[r][c4] =
            *(const uint4*)&g_qkvh[(size_t)(b * NL + qb + r) * 384 + h * 16 + c4];
    }

    const uint32_t q_ad = smQ + (uint32_t)((qw + (lane & 15)) * 20 + ((lane >> 4) << 2)) * 4;
    const uint32_t k_ad = smK + (uint32_t)(((lane & 7) + ((lane >> 4) << 3)) * 20 +
                                           (((lane >> 3) & 1) << 2)) * 4;
    const uint32_t v_ad = smV + (uint32_t)((lane & 15) * 20 + ((lane >> 4) << 2)) * 4;

    float o[2][4][4], lacc[2][4];
#pragma unroll
    for (int mt = 0; mt < 2; mt++) {
#pragma unroll
        for (int nt = 0; nt < 4; nt++)
#pragma unroll
            for (int j = 0; j < 4; j++) o[mt][nt][j] = 0.f;
#pragma unroll
        for (int j = 0; j < 4; j++) lacc[mt][j] = 0.f;
    }
    const uint32_t ones2[2] = {0x3C003C00u, 0x3C003C00u};  // fp16 1.0 x2

    // K/V chunk loader: 128 threads, 2 threads/row, 2 uint4 each per tensor
    const int fr = tid >> 1, fc = (tid & 1) * 8;

#define ATTN_ISSUE(kb, buf)                                                    \
    do {                                                                       \
        size_t base = (size_t)(b * NL + (kb) + fr) * 384 + h * 16 + fc;        \
        uint32_t off = (uint32_t)((buf) * 1280 + fr * 20 + fc) * 4;            \
        CP_ASYNC16(smK + off, &g_qkvh[base + 128]);                            \
        CP_ASYNC16(smK + off + 16, &g_qkvh[base + 132]);                       \
        CP_ASYNC16(smV + off, &g_qkvh[base + 256]);                            \
        CP_ASYNC16(smV + off + 16, &g_qkvh[base + 260]);                       \
    } while (0)

    ATTN_ISSUE(0, 0);
    CP_COMMIT();
    ATTN_ISSUE(64, 1);
    CP_COMMIT();
    __syncthreads();               // Qs visible -> load Q fragments once

    uint32_t qf[2][2][4];          // [m-frag][k-step]
#pragma unroll
    for (int mt = 0; mt < 2; mt++)
#pragma unroll
        for (int ks = 0; ks < 2; ks++)
            LDSM4(qf[mt][ks][0], qf[mt][ks][1], qf[mt][ks][2], qf[mt][ks][3],
                  q_ad + (uint32_t)(mt * 16 * 20 * 4) + ks * 32);

    int buf = 0;
#pragma unroll 1
    for (int it = 0; it < 16; it++) {
        if (it >= 14) CP_WAIT0(); else CP_WAIT1();
        __syncthreads();           // buffer 'it' visible; buffer (it-1)%3 free
        if (it < 14) {
            ATTN_ISSUE((it + 2) * 64, (buf + 2) % 3);
            CP_COMMIT();
        }
        const uint32_t boff = (uint32_t)(buf * 5120);

        // ---- S via fp16-accum MMA: output IS packed p-layout; exp in place.
        uint32_t p[2][8][2];
#pragma unroll
        for (int ntp = 0; ntp < 4; ntp++) {
            uint32_t da[2][2] = {{0u, 0u}, {0u, 0u}};   // [mt][reg]
            uint32_t db[2][2] = {{0u, 0u}, {0u, 0u}};
#pragma unroll
            for (int ks = 0; ks < 2; ks++) {
                uint32_t b0, b1, b2, b3;
                LDSM4(b0, b1, b2, b3, k_ad + boff + ntp * 1280 + ks * 32);
                uint32_t bfa[2] = {b0, b1};
                uint32_t bfb[2] = {b2, b3};
#pragma unroll
                for (int mt = 0; mt < 2; mt++) {
                    MMA_F16ACC(da[mt], qf[mt][ks], bfa);
                    MMA_F16ACC(db[mt], qf[mt][ks], bfb);
                }
            }
#pragma unroll
            for (int mt = 0; mt < 2; mt++) {
                EX2H2(da[mt][0]); EX2H2(da[mt][1]);
                EX2H2(db[mt][0]); EX2H2(db[mt][1]);
                p[mt][2 * ntp][0] = da[mt][0];
                p[mt][2 * ntp][1] = da[mt][1];
                p[mt][2 * ntp + 1][0] = db[mt][0];
                p[mt][2 * ntp + 1][1] = db[mt][1];
            }
        }

        // ---- O += P V ; l += P @ ones (fp32 accum).  V frags shared by mts.
#pragma unroll
        for (int ks = 0; ks < 4; ks++) {          // 16 keys per step
            uint32_t ap0[4] = {p[0][2 * ks][0], p[0][2 * ks][1],
                               p[0][2 * ks + 1][0], p[0][2 * ks + 1][1]};
            uint32_t ap1[4] = {p[1][2 * ks][0], p[1][2 * ks][1],
                               p[1][2 * ks + 1][0], p[1][2 * ks + 1][1]};
            MMA_F16(lacc[0], ap0, ones2);
            MMA_F16(lacc[1], ap1, ones2);
#pragma unroll
            for (int ntp = 0; ntp < 2; ntp++) {
                uint32_t b0, b1, b2, b3;
                LDSM4T(b0, b1, b2, b3, v_ad + boff + ks * 1280 + ntp * 32);
                uint32_t bfa[2] = {b0, b1};
                uint32_t bfb[2] = {b2, b3};
                MMA_F16(o[0][2 * ntp], ap0, bfa);
                MMA_F16(o[0][2 * ntp + 1], ap0, bfb);
                MMA_F16(o[1][2 * ntp], ap1, bfa);
                MMA_F16(o[1][2 * ntp + 1], ap1, bfb);
            }
        }
        buf = (buf + 1) % 3;
    }
#undef ATTN_ISSUE

#pragma unroll
    for (int mt = 0; mt < 2; mt++) {
        const float inv0 = 1.f / lacc[mt][0];
        const float inv1 = 1.f / lacc[mt][2];
        const int row = b * NL + qb + qw + mt * 16 + g;
#pragma unroll
        for (int nt = 0; nt < 4; nt++) {
            const int colw = h * 16 + nt * 4 + tg;
            uint32_t w0, w1;
            PACKF16(w0, o[mt][nt][0] * inv0, o[mt][nt][1] * inv0);
            PACKF16(w1, o[mt][nt][2] * inv1, o[mt][nt][3] * inv1);
            g_ctxh[(size_t)row * 128 + colw] = w0;
            g_ctxh[(size_t)(row + 8) * 128 + colw] = w1;
        }
    }
}

// ---------------------------------------------------------------------------
// Kernel 4: fused out-projection + residual + LayerNorm -> d_out.
// Block tile 64x256 (full rows), 8 warps (2m x 4n) of 32x64; K = 256.
// Single barrier per K-chunk.
// ---------------------------------------------------------------------------
#define OP_SMEM_WORDS (2 * 2304 + 2 * 9216)

__global__ void __launch_bounds__(256) outproj_ln_kernel(
    const uint32_t* __restrict__ Ctx, const uint32_t* __restrict__ Wh,
    const float* __restrict__ bias, float* __restrict__ outp) {
    extern __shared__ uint32_t sm[];
    __shared__ float s_sum[64][4], s_sq[64][4];
    const int tid = threadIdx.x, wid = tid >> 5, lane = tid & 31;
    const int g = lane >> 2, tg = lane & 3;
    const int m0 = blockIdx.x * 64;
    const int wm = (wid & 1) * 32, wn = (wid >> 1) * 64, nw = wid >> 1;
    const uint32_t smb = (uint32_t)__cvta_generic_to_shared(sm);
    const int a_r = lane & 15, a_c = (lane >> 4) * 4;
    const int b_r = (lane & 7) + ((lane >> 4) << 3), b_c = ((lane >> 3) & 1) * 4;

    float acc[2][8][4];
#pragma unroll
    for (int mt = 0; mt < 2; mt++)
#pragma unroll
        for (int nt = 0; nt < 8; nt++)
#pragma unroll
            for (int j = 0; j < 4; j++) acc[mt][nt][j] = 0.f;

#define OP_ISSUE(cc)                                                           \
    do {                                                                       \
        const int _s = (cc) & 1;                                               \
        _Pragma("unroll")                                                      \
        for (int it = 0; it < 2; it++) {                                       \
            int t = tid + it * 256;                                            \
            int r = t >> 3, c = (t & 7) * 4;                                   \
            CP_ASYNC16(smb + (uint32_t)(_s * 2304 + r * 36 + c) * 4,           \
                       &Ctx[(size_t)(m0 + r) * 128 + (cc) * 32 + c]);          \
        }                                                                      \
        _Pragma("unroll")                                                      \
        for (int it = 0; it < 8; it++) {                                       \
            int t = tid + it * 256;                                            \
            int r = t >> 3, c = (t & 7) * 4;                                   \
            CP_ASYNC16(smb + (uint32_t)(4608 + _s * 9216 + r * 36 + c) * 4,    \
                       &Wh[(size_t)r * 128 + (cc) * 32 + c]);                  \
        }                                                                      \
    } while (0)

    OP_ISSUE(0);
    CP_COMMIT();

#pragma unroll
    for (int cchunk = 0; cchunk < 4; cchunk++) {
        CP_WAIT0();
        __syncthreads();
        if (cchunk < 3) {
            OP_ISSUE(cchunk + 1);
            CP_COMMIT();
        }
        const uint32_t abase = smb + (uint32_t)((cchunk & 1) * 2304) * 4;
        const uint32_t bbase = smb + (uint32_t)(4608 + (cchunk & 1) * 9216) * 4;
#pragma unroll
        for (int ks = 0; ks < 4; ks++) {
            const int k0 = ks * 8;
            uint32_t af[2][4];
#pragma unroll
            for (int mt = 0; mt < 2; mt++)
                LDSM4(af[mt][0], af[mt][1], af[mt][2], af[mt][3],
                      abase + (uint32_t)((wm + mt * 16 + a_r) * 36 + k0 + a_c) * 4);
            uint32_t bf[8][2];
#pragma unroll
            for (int ntp = 0; ntp < 4; ntp++)
                LDSM4(bf[2 * ntp][0], bf[2 * ntp][1], bf[2 * ntp + 1][0], bf[2 * ntp + 1][1],
                      bbase + (uint32_t)((wn + ntp * 16 + b_r) * 36 + k0 + b_c) * 4);
#pragma unroll
            for (int mt = 0; mt < 2; mt++)
#pragma unroll
                for (int nt = 0; nt < 8; nt++)
                    MMA_F16(acc[mt][nt], af[mt], bf[nt]);
        }
    }
#undef OP_ISSUE

#pragma unroll
    for (int mt = 0; mt < 2; mt++)
#pragma unroll
        for (int nt = 0; nt < 8; nt++) {
            const int col = wn + nt * 8 + tg * 2;
            const int rA = m0 + wm + mt * 16 + g;
            const float b0 = bias[col], b1 = bias[col + 1];
            float2 eA = *(const float2*)&g_emb[(size_t)rA * 256 + col];
            float2 eB = *(const float2*)&g_emb[(size_t)(rA + 8) * 256 + col];
            acc[mt][nt][0] += b0 + eA.x;
            acc[mt][nt][1] += b1 + eA.y;
            acc[mt][nt][2] += b0 + eB.x;
            acc[mt][nt][3] += b1 + eB.y;
        }

#pragma unroll
    for (int mt = 0; mt < 2; mt++) {
        float sA = 0.f, qA = 0.f, sB = 0.f, qB = 0.f;
#pragma unroll
        for (int nt = 0; nt < 8; nt++) {
            sA += acc[mt][nt][0] + acc[mt][nt][1];
            qA += acc[mt][nt][0] * acc[mt][nt][0] + acc[mt][nt][1] * acc[mt][nt][1];
            sB += acc[mt][nt][2] + acc[mt][nt][3];
            qB += acc[mt][nt][2] * acc[mt][nt][2] + acc[mt][nt][3] * acc[mt][nt][3];
        }
#pragma unroll
        for (int off = 1; off < 4; off <<= 1) {
            sA += __shfl_xor_sync(0xffffffffu, sA, off);
            qA += __shfl_xor_sync(0xffffffffu, qA, off);
            sB += __shfl_xor_sync(0xffffffffu, sB, off);
            qB += __shfl_xor_sync(0xffffffffu, qB, off);
        }
        if (tg == 0) {
            const int lr = wm + mt * 16 + g;
            s_sum[lr][nw] = sA; s_sq[lr][nw] = qA;
            s_sum[lr + 8][nw] = sB; s_sq[lr + 8][nw] = qB;
        }
    }
    __syncthreads();

#pragma unroll
    for (int mt = 0; mt < 2; mt++) {
        const int lrA = wm + mt * 16 + g, lrB = lrA + 8;
        float tsA = s_sum[lrA][0] + s_sum[lrA][1] + s_sum[lrA][2] + s_sum[lrA][3];
        float tqA = s_sq[lrA][0] + s_sq[lrA][1] + s_sq[lrA][2] + s_sq[lrA][3];
        float tsB = s_sum[lrB][0] + s_sum[lrB][1] + s_sum[lrB][2] + s_sum[lrB][3];
        float tqB = s_sq[lrB][0] + s_sq[lrB][1] + s_sq[lrB][2] + s_sq[lrB][3];
        const float mA = tsA * (1.f / 256.f);
        const float rA = rsqrtf(tqA * (1.f / 256.f) - mA * mA + LN_EPS);
        const float mB = tsB * (1.f / 256.f);
        const float rB = rsqrtf(tqB * (1.f / 256.f) - mB * mB + LN_EPS);
#pragma unroll
        for (int nt = 0; nt < 8; nt++) {
            const int col = wn + nt * 8 + tg * 2;
            float2 vA = make_float2((acc[mt][nt][0] - mA) * rA,
                                    (acc[mt][nt][1] - mA) * rA);
            float2 vB = make_float2((acc[mt][nt][2] - mB) * rB,
                                    (acc[mt][nt][3] - mB) * rB);
            *(float2*)&outp[(size_t)(m0 + lrA) * 256 + col] = vA;
            *(float2*)&outp[(size_t)(m0 + lrB) * 256 + col] = vB;
        }
    }
}

// ---------------------------------------------------------------------------
extern "C" void kernel_launch(void* const* d_in, const int* in_sizes, int n_in,
                              void* d_out, int out_size) {
    const int*   seq   = (const int*)  d_in[0];
    const float* emb_w = (const float*)d_in[1];
    const float* emb_b = (const float*)d_in[2];
    const float* inp_w = (const float*)d_in[3];
    const float* inp_b = (const float*)d_in[4];
    const float* out_w = (const float*)d_in[5];
    const float* out_b = (const float*)d_in[6];
    float* out = (float*)d_out;

    uint32_t *p_embh, *p_qkvh, *p_ctxh, *p_wqkvh, *p_wouth;
    cudaGetSymbolAddress((void**)&p_embh, g_embh);
    cudaGetSymbolAddress((void**)&p_qkvh, g_qkvh);
    cudaGetSymbolAddress((void**)&p_ctxh, g_ctxh);
    cudaGetSymbolAddress((void**)&p_wqkvh, g_wqkvh);
    cudaGetSymbolAddress((void**)&p_wouth, g_wouth);

    const int gemm_smem = GEMM_SMEM_WORDS * 4;   // 73728
    const int op_smem = OP_SMEM_WORDS * 4;       // 92160
    cudaFuncSetAttribute(gemm_qkv_kernel,
                         cudaFuncAttributeMaxDynamicSharedMemorySize, gemm_smem);
    cudaFuncSetAttribute(outproj_ln_kernel,
                         cudaFuncAttributeMaxDynamicSharedMemorySize, op_smem);

    // 0. weight conversion fp32 -> fp16x2 (both matrices, one launch)
    cvtw_kernel<<<(NW1 + NW2 + 255) / 256, 256>>>(inp_w, out_w, p_wqkvh, p_wouth);
    // 1. embedding + LN (fp32 residual + fp16 copy), warp per row
    embed_ln_kernel<<<(NB * NL) / 8, 256>>>(seq, emb_w, emb_b);
    // 2. QKV projection -> packed fp16, Q pre-scaled by SC2F
    gemm_qkv_kernel<<<dim3(NE3 / 128, (NB * NL) / 128), 256, gemm_smem>>>(
        p_embh, p_wqkvh, inp_b, p_qkvh);
    // 3. fused flash attention -> g_ctxh (fp16), 128 threads / 4 warps
    attn_kernel<<<dim3(NL / 128, NH, NB), 128>>>();
    // 4. out-projection + residual + LN -> d_out
    outproj_ln_kernel<<<(NB * NL) / 64, 256, op_smem>>>(
        p_ctxh, p_wouth, out_b, out);
}